// round 2
// baseline (speedup 1.0000x reference)
#include <cuda_runtime.h>
#include <math.h>

#define MAXN 100000
#define I_CNT 128

// ---------------- device scratch (no allocations allowed) ----------------
__device__ float g_bufA[MAXN * 32];
__device__ float g_bufB[MAXN * 32];
__device__ float g_mask_feats[MAXN * 16];
__device__ float g_kern_feats[MAXN * 16];
__device__ float g_s[4 * MAXN];
__device__ int   g_bstart[8];
__device__ int   g_topk[I_CNT];
__device__ float g_ctr[I_CNT * 3];
__device__ float g_ck[I_CNT * 16];
__device__ float g_cm[I_CNT * 16];
__device__ int   g_cb[I_CNT];
__device__ float g_weights[I_CNT * 337];
__device__ float g_beff[I_CNT * 16];
__device__ float g_feat[I_CNT * 35];
__device__ float g_pairA[I_CNT * I_CNT * 35];
__device__ float g_pairB[I_CNT * I_CNT * 35];
__device__ double g_sum[64];
__device__ double g_sumsq[64];
__device__ float g_mean[64];
__device__ float g_rstd[64];

// ---------------- stats helpers ----------------
__global__ void zero_stats_kernel() {
    int t = threadIdx.x;
    if (t < 64) { g_sum[t] = 0.0; g_sumsq[t] = 0.0; }
}

__global__ void finalize_stats_kernel(int count, int dim) {
    int d = threadIdx.x;
    if (d < dim) {
        double m = g_sum[d] / (double)count;
        double v = g_sumsq[d] / (double)count - m * m;
        g_mean[d] = (float)m;
        g_rstd[d] = (float)(1.0 / sqrt(v + 1e-5));
    }
    if (d < 64) { g_sum[d] = 0.0; g_sumsq[d] = 0.0; }
}

// ---------------- generic MLP layer: out = (optional bn+relu of in) @ W (+bias) ----------------
template <int DIN, int DOUT, bool BN, bool STATS, bool BIAS>
__global__ __launch_bounds__(256) void layer_kernel(
    const float* __restrict__ in, const float* __restrict__ W,
    const float* __restrict__ bias, float* __restrict__ out, int N)
{
    __shared__ float Ws[DIN * DOUT];
    __shared__ float sb[DOUT];
    __shared__ float sm[DIN], sr[DIN];
    __shared__ double bs[DOUT], bq[DOUT];

    for (int t = threadIdx.x; t < DIN * DOUT; t += blockDim.x) Ws[t] = W[t];
    if (threadIdx.x < DOUT) sb[threadIdx.x] = BIAS ? bias[threadIdx.x] : 0.f;
    if (BN && threadIdx.x < DIN) {
        sm[threadIdx.x] = g_mean[threadIdx.x];
        sr[threadIdx.x] = g_rstd[threadIdx.x];
    }
    if (STATS && threadIdx.x < DOUT) { bs[threadIdx.x] = 0.0; bq[threadIdx.x] = 0.0; }
    __syncthreads();

    int n = blockIdx.x * blockDim.x + threadIdx.x;
    bool valid = (n < N);
    float acc[DOUT];
#pragma unroll
    for (int d = 0; d < DOUT; d++) acc[d] = sb[d];

    if (valid) {
#pragma unroll
        for (int c = 0; c < DIN; c++) {
            float xv = in[(size_t)n * DIN + c];
            if (BN) xv = fmaxf((xv - sm[c]) * sr[c], 0.f);
#pragma unroll
            for (int d = 0; d < DOUT; d++) acc[d] = fmaf(xv, Ws[c * DOUT + d], acc[d]);
        }
#pragma unroll
        for (int d = 0; d < DOUT; d++) out[(size_t)n * DOUT + d] = acc[d];
    }

    if (STATS) {
#pragma unroll
        for (int d = 0; d < DOUT; d++) {
            float v = valid ? acc[d] : 0.f;
            float v2 = v * v;
#pragma unroll
            for (int o = 16; o > 0; o >>= 1) {
                v  += __shfl_down_sync(0xffffffffu, v, o);
                v2 += __shfl_down_sync(0xffffffffu, v2, o);
            }
            if ((threadIdx.x & 31) == 0) {
                atomicAdd(&bs[d], (double)v);
                atomicAdd(&bq[d], (double)v2);
            }
        }
        __syncthreads();
        if (threadIdx.x < DOUT) {
            atomicAdd(&g_sum[threadIdx.x], bs[threadIdx.x]);
            atomicAdd(&g_sumsq[threadIdx.x], bq[threadIdx.x]);
        }
    }
}

// ---------------- batch ranges (batch_idxs sorted) ----------------
__global__ void batch_ranges_kernel(const int* __restrict__ bidx, int N) {
    int n = blockIdx.x * blockDim.x + threadIdx.x;
    if (n >= N) return;
    int b = bidx[n];
    int pb = (n == 0) ? -1 : bidx[n - 1];
    for (int x = pb + 1; x <= b; x++) g_bstart[x] = n;
    if (n == N - 1) for (int x = b + 1; x <= 4; x++) g_bstart[x] = N;
}

__global__ void nms_prep_kernel(const float* __restrict__ heat, int N) {
    int n = blockIdx.x * blockDim.x + threadIdx.x;
    if (n >= N) return;
    float h = heat[n];
#pragma unroll
    for (int b = 0; b < 4; b++) g_s[(size_t)b * N + n] = h;
}

// ---------------- sequential top-K NMS, one block per batch ----------------
__global__ __launch_bounds__(1024) void nms_kernel(const float* __restrict__ coords, int N) {
    int b = blockIdx.x;
    int s0 = g_bstart[b], s1 = g_bstart[b + 1];
    float* s = g_s + (size_t)b * N;
    __shared__ float wv[32];
    __shared__ int   wix[32];
    __shared__ float scx, scy, scz;
    int tid = threadIdx.x;

    for (int k = 0; k < 32; k++) {
        float bv = -INFINITY; int bi = 0;
        for (int n = s0 + tid; n < s1; n += 1024) {
            float v = s[n];
            if (v > bv || (v == bv && n < bi)) { bv = v; bi = n; }
        }
#pragma unroll
        for (int o = 16; o > 0; o >>= 1) {
            float ov = __shfl_down_sync(0xffffffffu, bv, o);
            int   oi = __shfl_down_sync(0xffffffffu, bi, o);
            if (ov > bv || (ov == bv && oi < bi)) { bv = ov; bi = oi; }
        }
        if ((tid & 31) == 0) { wv[tid >> 5] = bv; wix[tid >> 5] = bi; }
        __syncthreads();
        if (tid == 0) {
            float v = wv[0]; int ix = wix[0];
            for (int w = 1; w < 32; w++)
                if (wv[w] > v || (wv[w] == v && wix[w] < ix)) { v = wv[w]; ix = wix[w]; }
            g_topk[b * 32 + k] = ix;
            scx = coords[ix * 3]; scy = coords[ix * 3 + 1]; scz = coords[ix * 3 + 2];
        }
        __syncthreads();
        float cx = scx, cy = scy, cz = scz;
        // exact-rounding distance math (no FMA contraction) to match XLA
        for (int n = s0 + tid; n < s1; n += 1024) {
            float dx = __fadd_rn(coords[n * 3], -cx);
            float dy = __fadd_rn(coords[n * 3 + 1], -cy);
            float dz = __fadd_rn(coords[n * 3 + 2], -cz);
            float d2 = __fadd_rn(__fadd_rn(__fmul_rn(dx, dx), __fmul_rn(dy, dy)), __fmul_rn(dz, dz));
            if (d2 < 0.09f) s[n] = -INFINITY;
        }
        __syncthreads();
    }
}

// ---------------- gather selected candidates ----------------
__global__ void gather_kernel(const float* __restrict__ coords, const int* __restrict__ bidx) {
    int i = threadIdx.x;
    int idx = g_topk[i];
    float c0 = coords[idx * 3], c1 = coords[idx * 3 + 1], c2 = coords[idx * 3 + 2];
    g_ctr[i * 3] = c0; g_ctr[i * 3 + 1] = c1; g_ctr[i * 3 + 2] = c2;
    g_cb[i] = bidx[idx];
    for (int c = 0; c < 16; c++) {
        float kf = g_kern_feats[(size_t)idx * 16 + c];
        float mf = g_mask_feats[(size_t)idx * 16 + c];
        g_ck[i * 16 + c] = kf;
        g_cm[i * 16 + c] = mf;
        g_feat[i * 35 + c] = kf;
        g_feat[i * 35 + 16 + c] = mf;
    }
    g_feat[i * 35 + 32] = c0;
    g_feat[i * 35 + 33] = c1;
    g_feat[i * 35 + 34] = c2;
}

// ---------------- weight generator: weights = cand_kernel @ Wwg + bwg ----------------
__global__ void weights_kernel(const float* __restrict__ Wwg, const float* __restrict__ bwg) {
    int i = blockIdx.x, j = threadIdx.x;
    if (j >= 337) return;
    float a = bwg[j];
#pragma unroll
    for (int c = 0; c < 16; c++) a = fmaf(g_ck[i * 16 + c], Wwg[c * 337 + j], a);
    g_weights[i * 337 + j] = a;
}

// effective bias: b1 - ctr @ W1_pos  (folds pos = coords - ctr into bias)
__global__ void beff_kernel() {
    int i = blockIdx.x, h = threadIdx.x;
    const float* wi = g_weights + i * 337;
    float b = wi[304 + h];
#pragma unroll
    for (int p = 0; p < 3; p++) b -= g_ctr[i * 3 + p] * wi[(16 + p) * 16 + h];
    g_beff[i * 16 + h] = b;
}

// ---------------- dynamic-conv masks: the big kernel ----------------
// grid: (ceil(N/128), 4 instance-groups of 32), block 256.
// thread = (i_local = tid/8, hg = tid%8) handles 2 hidden channels of one instance,
// loops over the block's 128 points. 19x2 weights live in registers; z broadcast from smem.
__global__ __launch_bounds__(256) void masks_kernel(
    const float* __restrict__ coords, float* __restrict__ out, int N, int outw)
{
    __shared__ float zt[128][20];    // [point][19 features], padded
    __shared__ float ot[32][129];    // [i_local][point], padded (conflict-free col writes)

    int i_base = blockIdx.y * 32;
    int n0 = blockIdx.x * 128;
    int tid = threadIdx.x;
    int i_local = tid >> 3;
    int hg = tid & 7;
    int i = i_base + i_local;
    int h0 = hg * 2;

    const float* wi = g_weights + i * 337;
    float w0[19], w1[19];
#pragma unroll
    for (int r = 0; r < 19; r++) {
        w0[r] = wi[r * 16 + h0];
        w1[r] = wi[r * 16 + h0 + 1];
    }
    float be0 = g_beff[i * 16 + h0], be1 = g_beff[i * 16 + h0 + 1];
    float w2a = wi[320 + h0], w2b = wi[320 + h0 + 1];
    float b2 = wi[336];

    for (int idx = tid; idx < 128 * 16; idx += 256) {
        int p = idx >> 4, c = idx & 15;
        int n = n0 + p;
        zt[p][c] = (n < N) ? g_mask_feats[(size_t)n * 16 + c] : 0.f;
    }
    for (int idx = tid; idx < 128 * 3; idx += 256) {
        int p = idx / 3, c = idx % 3;
        int n = n0 + p;
        zt[p][16 + c] = (n < N) ? coords[(size_t)n * 3 + c] : 0.f;
    }
    __syncthreads();

    for (int p = 0; p < 128; p++) {
        float a0 = be0, a1 = be1;
#pragma unroll
        for (int r = 0; r < 19; r++) {
            float zv = zt[p][r];
            a0 = fmaf(zv, w0[r], a0);
            a1 = fmaf(zv, w1[r], a1);
        }
        float part = fmaxf(a0, 0.f) * w2a + fmaxf(a1, 0.f) * w2b;
        part += __shfl_down_sync(0xffffffffu, part, 4, 8);
        part += __shfl_down_sync(0xffffffffu, part, 2, 8);
        part += __shfl_down_sync(0xffffffffu, part, 1, 8);
        if (hg == 0) ot[i_local][p] = 1.f / (1.f + expf(-(part + b2)));
    }
    __syncthreads();

    // coalesced write-out: 32 rows x 128 cols
    for (int idx = tid; idx < 32 * 128; idx += 256) {
        int il = idx >> 7, p = idx & 127;
        int n = n0 + p;
        if (n < N) out[(size_t)(i_base + il) * outw + n] = ot[il][p];
    }
}

// ---------------- merge branch ----------------
__global__ void diff_kernel() {
    int p = blockIdx.x * blockDim.x + threadIdx.x;
    if (p >= I_CNT * I_CNT) return;
    int i = p >> 7, j = p & 127;
#pragma unroll
    for (int c = 0; c < 35; c++)
        g_pairA[(size_t)p * 35 + c] = fmaxf(fabsf(g_feat[i * 35 + c] - g_feat[j * 35 + c]), 1e-6f);
}

__global__ void merge_out_kernel(const float* __restrict__ WgOut, const float* __restrict__ bg,
                                 float* __restrict__ out, int N, int outw) {
    int p = blockIdx.x * blockDim.x + threadIdx.x;
    if (p >= I_CNT * I_CNT) return;
    int i = p >> 7, j = p & 127;
    float a = bg[0];
#pragma unroll
    for (int c = 0; c < 35; c++) {
        float xv = g_pairB[(size_t)p * 35 + c];
        xv = fmaxf((xv - g_mean[c]) * g_rstd[c], 0.f);
        a = fmaf(xv, WgOut[c], a);
    }
    float m = (g_cb[i] != g_cb[j]) ? 0.f : 1.f / (1.f + expf(-a));
    out[(size_t)i * outw + N + j] = m;
}

// ---------------- launcher ----------------
extern "C" void kernel_launch(void* const* d_in, const int* in_sizes, int n_in,
                              void* d_out, int out_size)
{
    const float* output_feats = (const float*)d_in[0];
    const float* coords       = (const float*)d_in[1];
    const float* heat         = (const float*)d_in[2];
    const int*   batch_idxs   = (const int*)d_in[3];
    const float* Wm     = (const float*)d_in[4];
    const float* Wm_out = (const float*)d_in[5];
    const float* bm_out = (const float*)d_in[6];
    const float* Wk     = (const float*)d_in[7];
    const float* Wk_out = (const float*)d_in[8];
    const float* bk_out = (const float*)d_in[9];
    const float* Wg     = (const float*)d_in[10];
    const float* Wg_out = (const float*)d_in[11];
    const float* bg_out = (const float*)d_in[12];
    const float* Wwg    = (const float*)d_in[13];
    const float* bwg    = (const float*)d_in[14];
    float* out = (float*)d_out;

    int N = in_sizes[2];           // heat element count
    int outw = N + I_CNT;
    int nb = (N + 255) / 256;

    float *bufA, *bufB, *maskf, *kernf, *pairA, *pairB;
    cudaGetSymbolAddress((void**)&bufA,  g_bufA);
    cudaGetSymbolAddress((void**)&bufB,  g_bufB);
    cudaGetSymbolAddress((void**)&maskf, g_mask_feats);
    cudaGetSymbolAddress((void**)&kernf, g_kern_feats);
    cudaGetSymbolAddress((void**)&pairA, g_pairA);
    cudaGetSymbolAddress((void**)&pairB, g_pairB);

    zero_stats_kernel<<<1, 64>>>();
    batch_ranges_kernel<<<nb, 256>>>(batch_idxs, N);
    nms_prep_kernel<<<nb, 256>>>(heat, N);
    nms_kernel<<<4, 1024>>>(coords, N);

    // mask tower
    layer_kernel<32, 32, false, true, false><<<nb, 256>>>(output_feats, Wm,        nullptr, bufA, N);
    finalize_stats_kernel<<<1, 64>>>(N, 32);
    layer_kernel<32, 32, true,  true, false><<<nb, 256>>>(bufA,         Wm + 1024, nullptr, bufB, N);
    finalize_stats_kernel<<<1, 64>>>(N, 32);
    layer_kernel<32, 32, true,  true, false><<<nb, 256>>>(bufB,         Wm + 2048, nullptr, bufA, N);
    finalize_stats_kernel<<<1, 64>>>(N, 32);
    layer_kernel<32, 16, true,  false, true><<<nb, 256>>>(bufA,         Wm_out,    bm_out,  maskf, N);

    // kernel tower
    layer_kernel<32, 32, false, true, false><<<nb, 256>>>(output_feats, Wk,        nullptr, bufA, N);
    finalize_stats_kernel<<<1, 64>>>(N, 32);
    layer_kernel<32, 32, true,  true, false><<<nb, 256>>>(bufA,         Wk + 1024, nullptr, bufB, N);
    finalize_stats_kernel<<<1, 64>>>(N, 32);
    layer_kernel<32, 32, true,  true, false><<<nb, 256>>>(bufB,         Wk + 2048, nullptr, bufA, N);
    finalize_stats_kernel<<<1, 64>>>(N, 32);
    layer_kernel<32, 16, true,  false, true><<<nb, 256>>>(bufA,         Wk_out,    bk_out,  kernf, N);

    gather_kernel<<<1, 128>>>(coords, batch_idxs);
    weights_kernel<<<128, 352>>>(Wwg, bwg);
    beff_kernel<<<128, 16>>>();

    dim3 mg((N + 127) / 128, 4);
    masks_kernel<<<mg, 256>>>(coords, out, N, outw);

    diff_kernel<<<64, 256>>>();
    layer_kernel<35, 35, false, true, false><<<64, 256>>>(pairA, Wg,        nullptr, pairB, I_CNT * I_CNT);
    finalize_stats_kernel<<<1, 64>>>(I_CNT * I_CNT, 35);
    layer_kernel<35, 35, true,  true, false><<<64, 256>>>(pairB, Wg + 1225, nullptr, pairA, I_CNT * I_CNT);
    finalize_stats_kernel<<<1, 64>>>(I_CNT * I_CNT, 35);
    layer_kernel<35, 35, true,  true, false><<<64, 256>>>(pairA, Wg + 2450, nullptr, pairB, I_CNT * I_CNT);
    finalize_stats_kernel<<<1, 64>>>(I_CNT * I_CNT, 35);
    merge_out_kernel<<<64, 256>>>(Wg_out, bg_out, out, N, outw);
}

// round 4
// speedup vs baseline: 1.0082x; 1.0082x over previous
#include <cuda_runtime.h>
#include <math.h>

#define MAXN 100000
#define I_CNT 128
#define NMS_CAP 50000

typedef unsigned long long ull;

// ---------------- device scratch (no allocations allowed) ----------------
__device__ float g_bufA[MAXN * 32];
__device__ float g_bufB[MAXN * 32];
__device__ float g_mask_feats[MAXN * 16];
__device__ float g_kern_feats[MAXN * 16];
__device__ float g_s[4 * MAXN];         // fallback only (batch > NMS_CAP)
__device__ int   g_bstart[8];
__device__ int   g_topk[I_CNT];
__device__ float g_ctr[I_CNT * 3];
__device__ float g_ck[I_CNT * 16];
__device__ float g_cm[I_CNT * 16];
__device__ int   g_cb[I_CNT];
__device__ float g_weights[I_CNT * 337];
__device__ float g_beff[I_CNT * 16];
__device__ float g_feat[I_CNT * 35];
__device__ float g_pairA[I_CNT * I_CNT * 35];
__device__ float g_pairB[I_CNT * I_CNT * 35];
__device__ double g_sum[64];
__device__ double g_sumsq[64];
__device__ float g_mean[64];
__device__ float g_rstd[64];

// ---------------- f32x2 helpers (exact fp32, 2x fma throughput) ----------------
__device__ __forceinline__ ull pk2(float lo, float hi) {
    ull r; asm("mov.b64 %0, {%1, %2};" : "=l"(r) : "f"(lo), "f"(hi)); return r;
}
__device__ __forceinline__ void upk2(ull v, float& lo, float& hi) {
    asm("mov.b64 {%0, %1}, %2;" : "=f"(lo), "=f"(hi) : "l"(v));
}
__device__ __forceinline__ ull ffma2(ull a, ull b, ull c) {
    ull d; asm("fma.rn.f32x2 %0, %1, %2, %3;" : "=l"(d) : "l"(a), "l"(b), "l"(c)); return d;
}

__device__ __forceinline__ float fast_sigmoid(float x) {
    return __fdividef(1.f, 1.f + __expf(-x));
}

// ---------------- stats helpers ----------------
__global__ void zero_stats_kernel() {
    int t = threadIdx.x;
    if (t < 64) { g_sum[t] = 0.0; g_sumsq[t] = 0.0; }
}

__global__ void finalize_stats_kernel(int count, int dim) {
    int d = threadIdx.x;
    if (d < dim) {
        double m = g_sum[d] / (double)count;
        double v = g_sumsq[d] / (double)count - m * m;
        g_mean[d] = (float)m;
        g_rstd[d] = (float)(1.0 / sqrt(v + 1e-5));
    }
    if (d < 64) { g_sum[d] = 0.0; g_sumsq[d] = 0.0; }
}

// ---------------- generic MLP layer: out = (optional bn+relu of in) @ W (+bias) ----------------
template <int DIN, int DOUT, bool BN, bool STATS, bool BIAS>
__global__ __launch_bounds__(256) void layer_kernel(
    const float* __restrict__ in, const float* __restrict__ W,
    const float* __restrict__ bias, float* __restrict__ out, int N)
{
    __shared__ float Ws[DIN * DOUT];
    __shared__ float sb[DOUT];
    __shared__ float sm[DIN], sr[DIN];
    __shared__ double bs[DOUT], bq[DOUT];

    for (int t = threadIdx.x; t < DIN * DOUT; t += blockDim.x) Ws[t] = W[t];
    if (threadIdx.x < DOUT) sb[threadIdx.x] = BIAS ? bias[threadIdx.x] : 0.f;
    if (BN && threadIdx.x < DIN) {
        sm[threadIdx.x] = g_mean[threadIdx.x];
        sr[threadIdx.x] = g_rstd[threadIdx.x];
    }
    if (STATS && threadIdx.x < DOUT) { bs[threadIdx.x] = 0.0; bq[threadIdx.x] = 0.0; }
    __syncthreads();

    int n = blockIdx.x * blockDim.x + threadIdx.x;
    bool valid = (n < N);
    float acc[DOUT];
#pragma unroll
    for (int d = 0; d < DOUT; d++) acc[d] = sb[d];

    if (valid) {
#pragma unroll
        for (int c = 0; c < DIN; c++) {
            float xv = in[(size_t)n * DIN + c];
            if (BN) xv = fmaxf((xv - sm[c]) * sr[c], 0.f);
#pragma unroll
            for (int d = 0; d < DOUT; d++) acc[d] = fmaf(xv, Ws[c * DOUT + d], acc[d]);
        }
#pragma unroll
        for (int d = 0; d < DOUT; d++) out[(size_t)n * DOUT + d] = acc[d];
    }

    if (STATS) {
#pragma unroll
        for (int d = 0; d < DOUT; d++) {
            float v = valid ? acc[d] : 0.f;
            float v2 = v * v;
#pragma unroll
            for (int o = 16; o > 0; o >>= 1) {
                v  += __shfl_down_sync(0xffffffffu, v, o);
                v2 += __shfl_down_sync(0xffffffffu, v2, o);
            }
            if ((threadIdx.x & 31) == 0) {
                atomicAdd(&bs[d], (double)v);
                atomicAdd(&bq[d], (double)v2);
            }
        }
        __syncthreads();
        if (threadIdx.x < DOUT) {
            atomicAdd(&g_sum[threadIdx.x], bs[threadIdx.x]);
            atomicAdd(&g_sumsq[threadIdx.x], bq[threadIdx.x]);
        }
    }
}

// ---------------- batch ranges (batch_idxs sorted) ----------------
__global__ void batch_ranges_kernel(const int* __restrict__ bidx, int N) {
    int n = blockIdx.x * blockDim.x + threadIdx.x;
    if (n >= N) return;
    int b = bidx[n];
    int pb = (n == 0) ? -1 : bidx[n - 1];
    for (int x = pb + 1; x <= b; x++) g_bstart[x] = n;
    if (n == N - 1) for (int x = b + 1; x <= 4; x++) g_bstart[x] = N;
}

// ---------------- fused top-K NMS: one block per batch, one scan per iteration ----------------
// Scores live in shared memory (200KB). Each iteration fuses suppression with the
// next argmax: per element, apply the suppress test locally, then track running max.
__global__ __launch_bounds__(1024) void nms_kernel(
    const float* __restrict__ heat, const float* __restrict__ coords, int N)
{
    extern __shared__ float ss[];
    __shared__ float wv[32];
    __shared__ int   wix[32];
    __shared__ float scx, scy, scz;

    int b = blockIdx.x, tid = threadIdx.x;
    int s0 = g_bstart[b], s1 = g_bstart[b + 1];
    int cnt = s1 - s0;
    float* s = (cnt <= NMS_CAP) ? (ss - s0) : (g_s + (size_t)b * N);

    // pass 0: fill scores + initial argmax
    float bv = -INFINITY; int bi = 0;
    for (int n = s0 + tid; n < s1; n += 1024) {
        float v = heat[n];
        s[n] = v;
        if (v > bv) { bv = v; bi = n; }   // strict > keeps earliest within thread
    }

    for (int k = 0; ; k++) {
        // block reduce (value, lowest-index tie)
#pragma unroll
        for (int o = 16; o > 0; o >>= 1) {
            float ov = __shfl_down_sync(0xffffffffu, bv, o);
            int   oi = __shfl_down_sync(0xffffffffu, bi, o);
            if (ov > bv || (ov == bv && oi < bi)) { bv = ov; bi = oi; }
        }
        if ((tid & 31) == 0) { wv[tid >> 5] = bv; wix[tid >> 5] = bi; }
        __syncthreads();
        if (tid < 32) {
            bv = wv[tid]; bi = wix[tid];
#pragma unroll
            for (int o = 16; o > 0; o >>= 1) {
                float ov = __shfl_down_sync(0xffffffffu, bv, o);
                int   oi = __shfl_down_sync(0xffffffffu, bi, o);
                if (ov > bv || (ov == bv && oi < bi)) { bv = ov; bi = oi; }
            }
            if (tid == 0) {
                g_topk[b * 32 + k] = bi;
                scx = coords[bi * 3]; scy = coords[bi * 3 + 1]; scz = coords[bi * 3 + 2];
            }
        }
        __syncthreads();
        if (k == 31) break;

        float cx = scx, cy = scy, cz = scz;
        // fused suppress + argmax scan (exact-rounding math, no FMA contraction)
        bv = -INFINITY; bi = 0;
#pragma unroll 4
        for (int n = s0 + tid; n < s1; n += 1024) {
            float v = s[n];
            if (v != -INFINITY) {
                float dx = __fadd_rn(coords[n * 3],     -cx);
                float dy = __fadd_rn(coords[n * 3 + 1], -cy);
                float dz = __fadd_rn(coords[n * 3 + 2], -cz);
                float d2 = __fadd_rn(__fadd_rn(__fmul_rn(dx, dx), __fmul_rn(dy, dy)),
                                     __fmul_rn(dz, dz));
                if (d2 < 0.09f) { v = -INFINITY; s[n] = v; }
            }
            if (v > bv || (v == bv && n < bi)) { bv = v; bi = n; }
        }
        // no sync needed: each warp only rewrites its own wv/wix slot; warp0's
        // read of wv/wix completed before the __syncthreads above.
    }
}

// ---------------- gather selected candidates ----------------
__global__ void gather_kernel(const float* __restrict__ coords, const int* __restrict__ bidx) {
    int i = threadIdx.x;
    int idx = g_topk[i];
    float c0 = coords[idx * 3], c1 = coords[idx * 3 + 1], c2 = coords[idx * 3 + 2];
    g_ctr[i * 3] = c0; g_ctr[i * 3 + 1] = c1; g_ctr[i * 3 + 2] = c2;
    g_cb[i] = bidx[idx];
    for (int c = 0; c < 16; c++) {
        float kf = g_kern_feats[(size_t)idx * 16 + c];
        float mf = g_mask_feats[(size_t)idx * 16 + c];
        g_ck[i * 16 + c] = kf;
        g_cm[i * 16 + c] = mf;
        g_feat[i * 35 + c] = kf;
        g_feat[i * 35 + 16 + c] = mf;
    }
    g_feat[i * 35 + 32] = c0;
    g_feat[i * 35 + 33] = c1;
    g_feat[i * 35 + 34] = c2;
}

// ---------------- weight generator: weights = cand_kernel @ Wwg + bwg ----------------
__global__ void weights_kernel(const float* __restrict__ Wwg, const float* __restrict__ bwg) {
    int i = blockIdx.x, j = threadIdx.x;
    if (j >= 337) return;
    float a = bwg[j];
#pragma unroll
    for (int c = 0; c < 16; c++) a = fmaf(g_ck[i * 16 + c], Wwg[c * 337 + j], a);
    g_weights[i * 337 + j] = a;
}

// effective bias: b1 - ctr @ W1_pos  (folds pos = coords - ctr into bias)
__global__ void beff_kernel() {
    int i = blockIdx.x, h = threadIdx.x;
    const float* wi = g_weights + i * 337;
    float b = wi[304 + h];
#pragma unroll
    for (int p = 0; p < 3; p++) b -= g_ctr[i * 3 + p] * wi[(16 + p) * 16 + h];
    g_beff[i * 16 + h] = b;
}

// ---------------- dynamic-conv masks: f32x2-packed point pairs ----------------
// block 256 = 32 instances x 8 channel-pair threads. z tile transposed to
// [feat][point] so a point-pair is one broadcast LDS.64; FFMA2 computes both
// points of a pair per instruction (exact fp32).
__global__ __launch_bounds__(256) void masks_kernel(
    const float* __restrict__ coords, float* __restrict__ out, int N, int outw)
{
    __shared__ __align__(16) float zs[19][130];   // [feature][point], 8B-aligned rows
    __shared__ float ot[32][130];                 // [i_local][point]

    int i_base = blockIdx.y * 32;
    int n0 = blockIdx.x * 128;
    int tid = threadIdx.x;
    int i_local = tid >> 3;
    int hg = tid & 7;
    int i = i_base + i_local;
    int h0 = hg * 2;

    const float* wi = g_weights + i * 337;
    ull w0[19], w1[19];
#pragma unroll
    for (int r = 0; r < 19; r++) {
        float a = wi[r * 16 + h0], b = wi[r * 16 + h0 + 1];
        w0[r] = pk2(a, a);
        w1[r] = pk2(b, b);
    }
    float be0f = g_beff[i * 16 + h0], be1f = g_beff[i * 16 + h0 + 1];
    ull be0 = pk2(be0f, be0f), be1 = pk2(be1f, be1f);
    float w2a = wi[320 + h0], w2b = wi[320 + h0 + 1];
    float b2 = wi[336];

    // stage transposed z tile
    for (int idx = tid; idx < 128 * 16; idx += 256) {
        int p = idx >> 4, c = idx & 15;
        int n = n0 + p;
        zs[c][p] = (n < N) ? g_mask_feats[(size_t)n * 16 + c] : 0.f;
    }
    for (int idx = tid; idx < 128 * 3; idx += 256) {
        int p = idx / 3, c = idx % 3;
        int n = n0 + p;
        zs[16 + c][p] = (n < N) ? coords[(size_t)n * 3 + c] : 0.f;
    }
    __syncthreads();

#pragma unroll 2
    for (int pp = 0; pp < 64; pp++) {
        ull a0 = be0, a1 = be1;
#pragma unroll
        for (int r = 0; r < 19; r++) {
            ull z = *(const ull*)&zs[r][pp * 2];   // LDS.64 broadcast
            a0 = ffma2(z, w0[r], a0);
            a1 = ffma2(z, w1[r], a1);
        }
        float a0l, a0h, a1l, a1h;
        upk2(a0, a0l, a0h);
        upk2(a1, a1l, a1h);
        float pl = fmaf(fmaxf(a0l, 0.f), w2a, fmaxf(a1l, 0.f) * w2b);
        float ph = fmaf(fmaxf(a0h, 0.f), w2a, fmaxf(a1h, 0.f) * w2b);
        pl += __shfl_down_sync(0xffffffffu, pl, 4, 8);
        ph += __shfl_down_sync(0xffffffffu, ph, 4, 8);
        pl += __shfl_down_sync(0xffffffffu, pl, 2, 8);
        ph += __shfl_down_sync(0xffffffffu, ph, 2, 8);
        pl += __shfl_down_sync(0xffffffffu, pl, 1, 8);
        ph += __shfl_down_sync(0xffffffffu, ph, 1, 8);
        if (hg == 0) {
            ot[i_local][pp * 2]     = fast_sigmoid(pl + b2);
            ot[i_local][pp * 2 + 1] = fast_sigmoid(ph + b2);
        }
    }
    __syncthreads();

    // coalesced write-out: 32 rows x 128 cols
    for (int idx = tid; idx < 32 * 128; idx += 256) {
        int il = idx >> 7, p = idx & 127;
        int n = n0 + p;
        if (n < N) out[(size_t)(i_base + il) * outw + n] = ot[il][p];
    }
}

// ---------------- merge branch ----------------
__global__ void diff_kernel() {
    int p = blockIdx.x * blockDim.x + threadIdx.x;
    if (p >= I_CNT * I_CNT) return;
    int i = p >> 7, j = p & 127;
#pragma unroll
    for (int c = 0; c < 35; c++)
        g_pairA[(size_t)p * 35 + c] = fmaxf(fabsf(g_feat[i * 35 + c] - g_feat[j * 35 + c]), 1e-6f);
}

__global__ void merge_out_kernel(const float* __restrict__ WgOut, const float* __restrict__ bg,
                                 float* __restrict__ out, int N, int outw) {
    int p = blockIdx.x * blockDim.x + threadIdx.x;
    if (p >= I_CNT * I_CNT) return;
    int i = p >> 7, j = p & 127;
    float a = bg[0];
#pragma unroll
    for (int c = 0; c < 35; c++) {
        float xv = g_pairB[(size_t)p * 35 + c];
        xv = fmaxf((xv - g_mean[c]) * g_rstd[c], 0.f);
        a = fmaf(xv, WgOut[c], a);
    }
    float m = (g_cb[i] != g_cb[j]) ? 0.f : fast_sigmoid(a);
    out[(size_t)i * outw + N + j] = m;
}

// ---------------- launcher ----------------
extern "C" void kernel_launch(void* const* d_in, const int* in_sizes, int n_in,
                              void* d_out, int out_size)
{
    const float* output_feats = (const float*)d_in[0];
    const float* coords       = (const float*)d_in[1];
    const float* heat         = (const float*)d_in[2];
    const int*   batch_idxs   = (const int*)d_in[3];
    const float* Wm     = (const float*)d_in[4];
    const float* Wm_out = (const float*)d_in[5];
    const float* bm_out = (const float*)d_in[6];
    const float* Wk     = (const float*)d_in[7];
    const float* Wk_out = (const float*)d_in[8];
    const float* bk_out = (const float*)d_in[9];
    const float* Wg     = (const float*)d_in[10];
    const float* Wg_out = (const float*)d_in[11];
    const float* bg_out = (const float*)d_in[12];
    const float* Wwg    = (const float*)d_in[13];
    const float* bwg    = (const float*)d_in[14];
    float* out = (float*)d_out;

    int N = in_sizes[2];           // heat element count
    int outw = N + I_CNT;
    int nb = (N + 255) / 256;

    float *bufA, *bufB, *maskf, *kernf, *pairA, *pairB;
    cudaGetSymbolAddress((void**)&bufA,  g_bufA);
    cudaGetSymbolAddress((void**)&bufB,  g_bufB);
    cudaGetSymbolAddress((void**)&maskf, g_mask_feats);
    cudaGetSymbolAddress((void**)&kernf, g_kern_feats);
    cudaGetSymbolAddress((void**)&pairA, g_pairA);
    cudaGetSymbolAddress((void**)&pairB, g_pairB);

    static bool attr_set = false;
    if (!attr_set) {
        cudaFuncSetAttribute(nms_kernel, cudaFuncAttributeMaxDynamicSharedMemorySize,
                             NMS_CAP * (int)sizeof(float));
        attr_set = true;
    }

    zero_stats_kernel<<<1, 64>>>();
    batch_ranges_kernel<<<nb, 256>>>(batch_idxs, N);
    nms_kernel<<<4, 1024, NMS_CAP * sizeof(float)>>>(heat, coords, N);

    // mask tower
    layer_kernel<32, 32, false, true, false><<<nb, 256>>>(output_feats, Wm,        nullptr, bufA, N);
    finalize_stats_kernel<<<1, 64>>>(N, 32);
    layer_kernel<32, 32, true,  true, false><<<nb, 256>>>(bufA,         Wm + 1024, nullptr, bufB, N);
    finalize_stats_kernel<<<1, 64>>>(N, 32);
    layer_kernel<32, 32, true,  true, false><<<nb, 256>>>(bufB,         Wm + 2048, nullptr, bufA, N);
    finalize_stats_kernel<<<1, 64>>>(N, 32);
    layer_kernel<32, 16, true,  false, true><<<nb, 256>>>(bufA,         Wm_out,    bm_out,  maskf, N);

    // kernel tower
    layer_kernel<32, 32, false, true, false><<<nb, 256>>>(output_feats, Wk,        nullptr, bufA, N);
    finalize_stats_kernel<<<1, 64>>>(N, 32);
    layer_kernel<32, 32, true,  true, false><<<nb, 256>>>(bufA,         Wk + 1024, nullptr, bufB, N);
    finalize_stats_kernel<<<1, 64>>>(N, 32);
    layer_kernel<32, 32, true,  true, false><<<nb, 256>>>(bufB,         Wk + 2048, nullptr, bufA, N);
    finalize_stats_kernel<<<1, 64>>>(N, 32);
    layer_kernel<32, 16, true,  false, true><<<nb, 256>>>(bufA,         Wk_out,    bk_out,  kernf, N);

    gather_kernel<<<1, 128>>>(coords, batch_idxs);
    weights_kernel<<<128, 352>>>(Wwg, bwg);
    beff_kernel<<<128, 16>>>();

    dim3 mg((N + 127) / 128, 4);
    masks_kernel<<<mg, 256>>>(coords, out, N, outw);

    diff_kernel<<<64, 256>>>();
    layer_kernel<35, 35, false, true, false><<<64, 256>>>(pairA, Wg,        nullptr, pairB, I_CNT * I_CNT);
    finalize_stats_kernel<<<1, 64>>>(I_CNT * I_CNT, 35);
    layer_kernel<35, 35, true,  true, false><<<64, 256>>>(pairB, Wg + 1225, nullptr, pairA, I_CNT * I_CNT);
    finalize_stats_kernel<<<1, 64>>>(I_CNT * I_CNT, 35);
    layer_kernel<35, 35, true,  true, false><<<64, 256>>>(pairA, Wg + 2450, nullptr, pairB, I_CNT * I_CNT);
    finalize_stats_kernel<<<1, 64>>>(I_CNT * I_CNT, 35);
    merge_out_kernel<<<64, 256>>>(Wg_out, bg_out, out, N, outw);
}

// round 5
// speedup vs baseline: 1.0928x; 1.0839x over previous
#include <cuda_runtime.h>
#include <math.h>

#define MAXN 100000
#define I_CNT 128
#define NMS_CAP 50000

typedef unsigned long long ull;

// ---------------- device scratch (no allocations allowed) ----------------
__device__ float g_tA[64 * MAXN];          // transposed activations [64][N]
__device__ float g_tB[64 * MAXN];
__device__ float g_mask_feats[16 * MAXN];  // transposed [16][N]
__device__ float g_kern_feats[16 * MAXN];  // transposed [16][N]
__device__ float g_s[4 * MAXN];            // nms fallback only
__device__ int   g_bstart[8];
__device__ int   g_topk[I_CNT];
__device__ float g_ctr[I_CNT * 3];
__device__ float g_ck[I_CNT * 16];
__device__ int   g_cb[I_CNT];
__device__ float g_weights[I_CNT * 337];
__device__ float g_beff[I_CNT * 16];
__device__ float g_feat[I_CNT * 35];
__device__ float g_pairA[I_CNT * I_CNT * 35];
__device__ float g_pairB[I_CNT * I_CNT * 35];
__device__ double g_sum[64];
__device__ double g_sumsq[64];
__device__ float g_mean[64];
__device__ float g_rstd[64];
__device__ unsigned int g_cnt;

// ---------------- f32x2 helpers (exact fp32, 2x fma throughput) ----------------
__device__ __forceinline__ ull pk2(float lo, float hi) {
    ull r; asm("mov.b64 %0, {%1, %2};" : "=l"(r) : "f"(lo), "f"(hi)); return r;
}
__device__ __forceinline__ void upk2(ull v, float& lo, float& hi) {
    asm("mov.b64 {%0, %1}, %2;" : "=f"(lo), "=f"(hi) : "l"(v));
}
__device__ __forceinline__ ull ffma2(ull a, ull b, ull c) {
    ull d; asm("fma.rn.f32x2 %0, %1, %2, %3;" : "=l"(d) : "l"(a), "l"(b), "l"(c)); return d;
}
__device__ __forceinline__ float fast_sigmoid(float x) {
    return __fdividef(1.f, 1.f + __expf(-x));
}

// ---------------- stats helpers (merge-branch path) ----------------
__global__ void zero_stats_kernel() {
    int t = threadIdx.x;
    if (t < 64) { g_sum[t] = 0.0; g_sumsq[t] = 0.0; }
    if (t == 0) g_cnt = 0;
}

__global__ void finalize_stats_kernel(int count, int dim) {
    int d = threadIdx.x;
    if (d < dim) {
        double m = g_sum[d] / (double)count;
        double v = g_sumsq[d] / (double)count - m * m;
        g_mean[d] = (float)m;
        g_rstd[d] = (float)(1.0 / sqrt(v + 1e-5));
    }
    if (d < 64) { g_sum[d] = 0.0; g_sumsq[d] = 0.0; }
}

// ---------------- fused tower layer 0: row-major input, smem transpose ----------------
// out[d][n] (d<32: mask tower, d>=32: kernel tower), both computed via f32x2.
__global__ __launch_bounds__(256) void layer0_kernel(
    const float* __restrict__ in,          // [N][32] row-major
    const float* __restrict__ Wm, const float* __restrict__ Wk,  // [32][32]
    float* __restrict__ out, int N)        // [64][N]
{
    __shared__ float xs[256][33];
    __shared__ ull wp[1024];

    int tid = threadIdx.x;
    for (int t = tid; t < 1024; t += 256) wp[t] = pk2(Wm[t], Wk[t]);

    int n0 = blockIdx.x * 256;
    int npts = N - n0; if (npts > 256) npts = 256;
    for (int idx = tid; idx < npts * 32; idx += 256)
        xs[idx >> 5][idx & 31] = in[(size_t)n0 * 32 + idx];
    __syncthreads();

    if (tid >= npts) return;
    int n = n0 + tid;

    ull acc[32];
#pragma unroll
    for (int d = 0; d < 32; d++) acc[d] = 0ull;

#pragma unroll
    for (int c = 0; c < 32; c++) {
        float z = xs[tid][c];
        ull zz = pk2(z, z);
        const ull* w = &wp[c * 32];
#pragma unroll
        for (int d = 0; d < 32; d++) acc[d] = ffma2(zz, w[d], acc[d]);
    }
#pragma unroll
    for (int d = 0; d < 32; d++) {
        float lo, hi; upk2(acc[d], lo, hi);
        out[(size_t)d * N + n] = lo;
        out[(size_t)(32 + d) * N + n] = hi;
    }
}

// ---------------- fused tower BN layer: transposed in/out ----------------
__global__ __launch_bounds__(256) void layerBN_kernel(
    const float* __restrict__ in,          // [64][N]
    const float* __restrict__ Wm, const float* __restrict__ Wk,  // [32][32]
    float* __restrict__ out, int N)        // [64][N]
{
    __shared__ ull wp[1024];
    __shared__ float sm[64], sr[64];
    int tid = threadIdx.x;
    for (int t = tid; t < 1024; t += 256) wp[t] = pk2(Wm[t], Wk[t]);
    if (tid < 64) { sm[tid] = g_mean[tid]; sr[tid] = g_rstd[tid]; }
    __syncthreads();

    int n = blockIdx.x * 256 + tid;
    if (n >= N) return;

    ull acc[32];
#pragma unroll
    for (int d = 0; d < 32; d++) acc[d] = 0ull;

#pragma unroll
    for (int c = 0; c < 32; c++) {
        float xm = in[(size_t)c * N + n];
        float xk = in[(size_t)(32 + c) * N + n];
        xm = fmaxf((xm - sm[c]) * sr[c], 0.f);
        xk = fmaxf((xk - sm[32 + c]) * sr[32 + c], 0.f);
        ull zz = pk2(xm, xk);
        const ull* w = &wp[c * 32];
#pragma unroll
        for (int d = 0; d < 32; d++) acc[d] = ffma2(zz, w[d], acc[d]);
    }
#pragma unroll
    for (int d = 0; d < 32; d++) {
        float lo, hi; upk2(acc[d], lo, hi);
        out[(size_t)d * N + n] = lo;
        out[(size_t)(32 + d) * N + n] = hi;
    }
}

// ---------------- fused tower output layer: 64 -> 16+16, with bias ----------------
__global__ __launch_bounds__(256) void layerOut_kernel(
    const float* __restrict__ in,          // [64][N]
    const float* __restrict__ WmO, const float* __restrict__ WkO,  // [32][16]
    const float* __restrict__ bm, const float* __restrict__ bk,    // [16]
    float* __restrict__ om, float* __restrict__ ok, int N)         // [16][N] each
{
    __shared__ ull wp[512];
    __shared__ float sm[64], sr[64];
    __shared__ ull bb[16];
    int tid = threadIdx.x;
    for (int t = tid; t < 512; t += 256) wp[t] = pk2(WmO[t], WkO[t]);
    if (tid < 64) { sm[tid] = g_mean[tid]; sr[tid] = g_rstd[tid]; }
    if (tid < 16) bb[tid] = pk2(bm[tid], bk[tid]);
    __syncthreads();

    int n = blockIdx.x * 256 + tid;
    if (n >= N) return;

    ull acc[16];
#pragma unroll
    for (int d = 0; d < 16; d++) acc[d] = bb[d];

#pragma unroll
    for (int c = 0; c < 32; c++) {
        float xm = in[(size_t)c * N + n];
        float xk = in[(size_t)(32 + c) * N + n];
        xm = fmaxf((xm - sm[c]) * sr[c], 0.f);
        xk = fmaxf((xk - sm[32 + c]) * sr[32 + c], 0.f);
        ull zz = pk2(xm, xk);
        const ull* w = &wp[c * 16];
#pragma unroll
        for (int d = 0; d < 16; d++) acc[d] = ffma2(zz, w[d], acc[d]);
    }
#pragma unroll
    for (int d = 0; d < 16; d++) {
        float lo, hi; upk2(acc[d], lo, hi);
        om[(size_t)d * N + n] = lo;
        ok[(size_t)d * N + n] = hi;
    }
}

// ---------------- stats over transposed activations [64][N]; last block finalizes ----------------
__global__ __launch_bounds__(256) void stats64_kernel(const float* __restrict__ in, int N)
{
    int c = blockIdx.y;
    int tid = threadIdx.x;
    float s = 0.f, q = 0.f;
    for (int n = blockIdx.x * 256 + tid; n < N; n += 256 * gridDim.x) {
        float v = in[(size_t)c * N + n];
        s += v; q = fmaf(v, v, q);
    }
#pragma unroll
    for (int o = 16; o > 0; o >>= 1) {
        s += __shfl_down_sync(0xffffffffu, s, o);
        q += __shfl_down_sync(0xffffffffu, q, o);
    }
    __shared__ float ws[8], wq[8];
    if ((tid & 31) == 0) { ws[tid >> 5] = s; wq[tid >> 5] = q; }
    __syncthreads();
    if (tid == 0) {
        for (int w = 1; w < 8; w++) { s += ws[w]; q += wq[w]; }
        atomicAdd(&g_sum[c], (double)s);
        atomicAdd(&g_sumsq[c], (double)q);
        __threadfence();
        unsigned int t = atomicAdd(&g_cnt, 1u);
        if (t == gridDim.x * gridDim.y - 1) {
            for (int ch = 0; ch < 64; ch++) {
                double m = g_sum[ch] / (double)N;
                double v = g_sumsq[ch] / (double)N - m * m;
                g_mean[ch] = (float)m;
                g_rstd[ch] = (float)(1.0 / sqrt(v + 1e-5));
                g_sum[ch] = 0.0; g_sumsq[ch] = 0.0;
            }
            g_cnt = 0;
        }
    }
}

// ---------------- merge-branch generic layer (row-major, small) ----------------
template <int DIN, int DOUT, bool BN, bool STATS, bool BIAS>
__global__ __launch_bounds__(256) void layer_kernel(
    const float* __restrict__ in, const float* __restrict__ W,
    const float* __restrict__ bias, float* __restrict__ out, int N)
{
    __shared__ float Ws[DIN * DOUT];
    __shared__ float sb[DOUT];
    __shared__ float sm[DIN], sr[DIN];
    __shared__ double bs[DOUT], bq[DOUT];

    for (int t = threadIdx.x; t < DIN * DOUT; t += blockDim.x) Ws[t] = W[t];
    if (threadIdx.x < DOUT) sb[threadIdx.x] = BIAS ? bias[threadIdx.x] : 0.f;
    if (BN && threadIdx.x < DIN) {
        sm[threadIdx.x] = g_mean[threadIdx.x];
        sr[threadIdx.x] = g_rstd[threadIdx.x];
    }
    if (STATS && threadIdx.x < DOUT) { bs[threadIdx.x] = 0.0; bq[threadIdx.x] = 0.0; }
    __syncthreads();

    int n = blockIdx.x * blockDim.x + threadIdx.x;
    bool valid = (n < N);
    float acc[DOUT];
#pragma unroll
    for (int d = 0; d < DOUT; d++) acc[d] = sb[d];

    if (valid) {
#pragma unroll
        for (int c = 0; c < DIN; c++) {
            float xv = in[(size_t)n * DIN + c];
            if (BN) xv = fmaxf((xv - sm[c]) * sr[c], 0.f);
#pragma unroll
            for (int d = 0; d < DOUT; d++) acc[d] = fmaf(xv, Ws[c * DOUT + d], acc[d]);
        }
#pragma unroll
        for (int d = 0; d < DOUT; d++) out[(size_t)n * DOUT + d] = acc[d];
    }

    if (STATS) {
#pragma unroll
        for (int d = 0; d < DOUT; d++) {
            float v = valid ? acc[d] : 0.f;
            float v2 = v * v;
#pragma unroll
            for (int o = 16; o > 0; o >>= 1) {
                v  += __shfl_down_sync(0xffffffffu, v, o);
                v2 += __shfl_down_sync(0xffffffffu, v2, o);
            }
            if ((threadIdx.x & 31) == 0) {
                atomicAdd(&bs[d], (double)v);
                atomicAdd(&bq[d], (double)v2);
            }
        }
        __syncthreads();
        if (threadIdx.x < DOUT) {
            atomicAdd(&g_sum[threadIdx.x], bs[threadIdx.x]);
            atomicAdd(&g_sumsq[threadIdx.x], bq[threadIdx.x]);
        }
    }
}

// ---------------- batch ranges (batch_idxs sorted) ----------------
__global__ void batch_ranges_kernel(const int* __restrict__ bidx, int N) {
    int n = blockIdx.x * blockDim.x + threadIdx.x;
    if (n >= N) return;
    int b = bidx[n];
    int pb = (n == 0) ? -1 : bidx[n - 1];
    for (int x = pb + 1; x <= b; x++) g_bstart[x] = n;
    if (n == N - 1) for (int x = b + 1; x <= 4; x++) g_bstart[x] = N;
}

// ---------------- fused top-K NMS ----------------
__global__ __launch_bounds__(1024) void nms_kernel(
    const float* __restrict__ heat, const float* __restrict__ coords, int N)
{
    extern __shared__ float ss[];
    __shared__ float wv[32];
    __shared__ int   wix[32];
    __shared__ float scx, scy, scz;

    int b = blockIdx.x, tid = threadIdx.x;
    int s0 = g_bstart[b], s1 = g_bstart[b + 1];
    int cnt = s1 - s0;
    float* s = (cnt <= NMS_CAP) ? (ss - s0) : (g_s + (size_t)b * N);

    float bv = -INFINITY; int bi = 0;
    for (int n = s0 + tid; n < s1; n += 1024) {
        float v = heat[n];
        s[n] = v;
        if (v > bv) { bv = v; bi = n; }
    }

    for (int k = 0; ; k++) {
#pragma unroll
        for (int o = 16; o > 0; o >>= 1) {
            float ov = __shfl_down_sync(0xffffffffu, bv, o);
            int   oi = __shfl_down_sync(0xffffffffu, bi, o);
            if (ov > bv || (ov == bv && oi < bi)) { bv = ov; bi = oi; }
        }
        if ((tid & 31) == 0) { wv[tid >> 5] = bv; wix[tid >> 5] = bi; }
        __syncthreads();
        if (tid < 32) {
            bv = wv[tid]; bi = wix[tid];
#pragma unroll
            for (int o = 16; o > 0; o >>= 1) {
                float ov = __shfl_down_sync(0xffffffffu, bv, o);
                int   oi = __shfl_down_sync(0xffffffffu, bi, o);
                if (ov > bv || (ov == bv && oi < bi)) { bv = ov; bi = oi; }
            }
            if (tid == 0) {
                g_topk[b * 32 + k] = bi;
                scx = coords[bi * 3]; scy = coords[bi * 3 + 1]; scz = coords[bi * 3 + 2];
            }
        }
        __syncthreads();
        if (k == 31) break;

        float cx = scx, cy = scy, cz = scz;
        bv = -INFINITY; bi = 0;
#pragma unroll 4
        for (int n = s0 + tid; n < s1; n += 1024) {
            float v = s[n];
            if (v != -INFINITY) {
                float dx = __fadd_rn(coords[n * 3],     -cx);
                float dy = __fadd_rn(coords[n * 3 + 1], -cy);
                float dz = __fadd_rn(coords[n * 3 + 2], -cz);
                float d2 = __fadd_rn(__fadd_rn(__fmul_rn(dx, dx), __fmul_rn(dy, dy)),
                                     __fmul_rn(dz, dz));
                if (d2 < 0.09f) { v = -INFINITY; s[n] = v; }
            }
            if (v > bv || (v == bv && n < bi)) { bv = v; bi = n; }
        }
    }
}

// ---------------- gather selected candidates (transposed feats) ----------------
__global__ void gather_kernel(const float* __restrict__ coords, const int* __restrict__ bidx, int N) {
    int i = threadIdx.x;
    int idx = g_topk[i];
    float c0 = coords[idx * 3], c1 = coords[idx * 3 + 1], c2 = coords[idx * 3 + 2];
    g_ctr[i * 3] = c0; g_ctr[i * 3 + 1] = c1; g_ctr[i * 3 + 2] = c2;
    g_cb[i] = bidx[idx];
    for (int c = 0; c < 16; c++) {
        float kf = g_kern_feats[(size_t)c * N + idx];
        float mf = g_mask_feats[(size_t)c * N + idx];
        g_ck[i * 16 + c] = kf;
        g_feat[i * 35 + c] = kf;
        g_feat[i * 35 + 16 + c] = mf;
    }
    g_feat[i * 35 + 32] = c0;
    g_feat[i * 35 + 33] = c1;
    g_feat[i * 35 + 34] = c2;
}

// ---------------- weight generator ----------------
__global__ void weights_kernel(const float* __restrict__ Wwg, const float* __restrict__ bwg) {
    int i = blockIdx.x, j = threadIdx.x;
    if (j >= 337) return;
    float a = bwg[j];
#pragma unroll
    for (int c = 0; c < 16; c++) a = fmaf(g_ck[i * 16 + c], Wwg[c * 337 + j], a);
    g_weights[i * 337 + j] = a;
}

__global__ void beff_kernel() {
    int i = blockIdx.x, h = threadIdx.x;
    const float* wi = g_weights + i * 337;
    float b = wi[304 + h];
#pragma unroll
    for (int p = 0; p < 3; p++) b -= g_ctr[i * 3 + p] * wi[(16 + p) * 16 + h];
    g_beff[i * 16 + h] = b;
}

// ---------------- dynamic-conv masks (transposed mask_feats) ----------------
__global__ __launch_bounds__(256) void masks_kernel(
    const float* __restrict__ coords, float* __restrict__ out, int N, int outw)
{
    __shared__ __align__(16) float zs[19][130];
    __shared__ float ot[32][130];

    int i_base = blockIdx.y * 32;
    int n0 = blockIdx.x * 128;
    int tid = threadIdx.x;
    int i_local = tid >> 3;
    int hg = tid & 7;
    int i = i_base + i_local;
    int h0 = hg * 2;

    const float* wi = g_weights + i * 337;
    ull w0[19], w1[19];
#pragma unroll
    for (int r = 0; r < 19; r++) {
        float a = wi[r * 16 + h0], b = wi[r * 16 + h0 + 1];
        w0[r] = pk2(a, a);
        w1[r] = pk2(b, b);
    }
    float be0f = g_beff[i * 16 + h0], be1f = g_beff[i * 16 + h0 + 1];
    ull be0 = pk2(be0f, be0f), be1 = pk2(be1f, be1f);
    float w2a = wi[320 + h0], w2b = wi[320 + h0 + 1];
    float b2 = wi[336];

    // coalesced staging from transposed mask_feats
    for (int idx = tid; idx < 16 * 128; idx += 256) {
        int c = idx >> 7, p = idx & 127;
        int n = n0 + p;
        zs[c][p] = (n < N) ? g_mask_feats[(size_t)c * N + n] : 0.f;
    }
    for (int idx = tid; idx < 128 * 3; idx += 256) {
        int p = idx / 3, c = idx % 3;
        int n = n0 + p;
        zs[16 + c][p] = (n < N) ? coords[(size_t)n * 3 + c] : 0.f;
    }
    __syncthreads();

#pragma unroll 2
    for (int pp = 0; pp < 64; pp++) {
        ull a0 = be0, a1 = be1;
#pragma unroll
        for (int r = 0; r < 19; r++) {
            ull z = *(const ull*)&zs[r][pp * 2];
            a0 = ffma2(z, w0[r], a0);
            a1 = ffma2(z, w1[r], a1);
        }
        float a0l, a0h, a1l, a1h;
        upk2(a0, a0l, a0h);
        upk2(a1, a1l, a1h);
        float pl = fmaf(fmaxf(a0l, 0.f), w2a, fmaxf(a1l, 0.f) * w2b);
        float ph = fmaf(fmaxf(a0h, 0.f), w2a, fmaxf(a1h, 0.f) * w2b);
        pl += __shfl_down_sync(0xffffffffu, pl, 4, 8);
        ph += __shfl_down_sync(0xffffffffu, ph, 4, 8);
        pl += __shfl_down_sync(0xffffffffu, pl, 2, 8);
        ph += __shfl_down_sync(0xffffffffu, ph, 2, 8);
        pl += __shfl_down_sync(0xffffffffu, pl, 1, 8);
        ph += __shfl_down_sync(0xffffffffu, ph, 1, 8);
        if (hg == 0) {
            ot[i_local][pp * 2]     = fast_sigmoid(pl + b2);
            ot[i_local][pp * 2 + 1] = fast_sigmoid(ph + b2);
        }
    }
    __syncthreads();

    for (int idx = tid; idx < 32 * 128; idx += 256) {
        int il = idx >> 7, p = idx & 127;
        int n = n0 + p;
        if (n < N) out[(size_t)(i_base + il) * outw + n] = ot[il][p];
    }
}

// ---------------- merge branch ----------------
__global__ void diff_kernel() {
    int p = blockIdx.x * blockDim.x + threadIdx.x;
    if (p >= I_CNT * I_CNT) return;
    int i = p >> 7, j = p & 127;
#pragma unroll
    for (int c = 0; c < 35; c++)
        g_pairA[(size_t)p * 35 + c] = fmaxf(fabsf(g_feat[i * 35 + c] - g_feat[j * 35 + c]), 1e-6f);
}

__global__ void merge_out_kernel(const float* __restrict__ WgOut, const float* __restrict__ bg,
                                 float* __restrict__ out, int N, int outw) {
    int p = blockIdx.x * blockDim.x + threadIdx.x;
    if (p >= I_CNT * I_CNT) return;
    int i = p >> 7, j = p & 127;
    float a = bg[0];
#pragma unroll
    for (int c = 0; c < 35; c++) {
        float xv = g_pairB[(size_t)p * 35 + c];
        xv = fmaxf((xv - g_mean[c]) * g_rstd[c], 0.f);
        a = fmaf(xv, WgOut[c], a);
    }
    float m = (g_cb[i] != g_cb[j]) ? 0.f : fast_sigmoid(a);
    out[(size_t)i * outw + N + j] = m;
}

// ---------------- launcher ----------------
extern "C" void kernel_launch(void* const* d_in, const int* in_sizes, int n_in,
                              void* d_out, int out_size)
{
    const float* output_feats = (const float*)d_in[0];
    const float* coords       = (const float*)d_in[1];
    const float* heat         = (const float*)d_in[2];
    const int*   batch_idxs   = (const int*)d_in[3];
    const float* Wm     = (const float*)d_in[4];
    const float* Wm_out = (const float*)d_in[5];
    const float* bm_out = (const float*)d_in[6];
    const float* Wk     = (const float*)d_in[7];
    const float* Wk_out = (const float*)d_in[8];
    const float* bk_out = (const float*)d_in[9];
    const float* Wg     = (const float*)d_in[10];
    const float* Wg_out = (const float*)d_in[11];
    const float* bg_out = (const float*)d_in[12];
    const float* Wwg    = (const float*)d_in[13];
    const float* bwg    = (const float*)d_in[14];
    float* out = (float*)d_out;

    int N = in_sizes[2];
    int outw = N + I_CNT;
    int nb = (N + 255) / 256;

    float *tA, *tB, *maskf, *kernf, *pairA, *pairB;
    cudaGetSymbolAddress((void**)&tA,    g_tA);
    cudaGetSymbolAddress((void**)&tB,    g_tB);
    cudaGetSymbolAddress((void**)&maskf, g_mask_feats);
    cudaGetSymbolAddress((void**)&kernf, g_kern_feats);
    cudaGetSymbolAddress((void**)&pairA, g_pairA);
    cudaGetSymbolAddress((void**)&pairB, g_pairB);

    static bool attr_set = false;
    if (!attr_set) {
        cudaFuncSetAttribute(nms_kernel, cudaFuncAttributeMaxDynamicSharedMemorySize,
                             NMS_CAP * (int)sizeof(float));
        attr_set = true;
    }

    dim3 sg(8, 64);

    zero_stats_kernel<<<1, 64>>>();
    batch_ranges_kernel<<<nb, 256>>>(batch_idxs, N);
    nms_kernel<<<4, 1024, NMS_CAP * sizeof(float)>>>(heat, coords, N);

    // fused towers (mask + kernel in one pass, f32x2-packed)
    layer0_kernel<<<nb, 256>>>(output_feats, Wm, Wk, tA, N);
    stats64_kernel<<<sg, 256>>>(tA, N);
    layerBN_kernel<<<nb, 256>>>(tA, Wm + 1024, Wk + 1024, tB, N);
    stats64_kernel<<<sg, 256>>>(tB, N);
    layerBN_kernel<<<nb, 256>>>(tB, Wm + 2048, Wk + 2048, tA, N);
    stats64_kernel<<<sg, 256>>>(tA, N);
    layerOut_kernel<<<nb, 256>>>(tA, Wm_out, Wk_out, bm_out, bk_out, maskf, kernf, N);

    gather_kernel<<<1, 128>>>(coords, batch_idxs, N);
    weights_kernel<<<128, 352>>>(Wwg, bwg);
    beff_kernel<<<128, 16>>>();

    dim3 mg((N + 127) / 128, 4);
    masks_kernel<<<mg, 256>>>(coords, out, N, outw);

    diff_kernel<<<64, 256>>>();
    layer_kernel<35, 35, false, true, false><<<64, 256>>>(pairA, Wg,        nullptr, pairB, I_CNT * I_CNT);
    finalize_stats_kernel<<<1, 64>>>(I_CNT * I_CNT, 35);
    layer_kernel<35, 35, true,  true, false><<<64, 256>>>(pairB, Wg + 1225, nullptr, pairA, I_CNT * I_CNT);
    finalize_stats_kernel<<<1, 64>>>(I_CNT * I_CNT, 35);
    layer_kernel<35, 35, true,  true, false><<<64, 256>>>(pairA, Wg + 2450, nullptr, pairB, I_CNT * I_CNT);
    finalize_stats_kernel<<<1, 64>>>(I_CNT * I_CNT, 35);
    merge_out_kernel<<<64, 256>>>(Wg_out, bg_out, out, N, outw);
}

// round 6
// speedup vs baseline: 1.4245x; 1.3035x over previous
#include <cuda_runtime.h>
#include <math.h>

#define MAXN 100000
#define I_CNT 128
#define NMS_CAP 50000
#define MTILE 256

typedef unsigned long long ull;

// ---------------- device scratch (no allocations allowed) ----------------
__device__ float g_tA[64 * MAXN];          // transposed activations [64][N]
__device__ float g_tB[64 * MAXN];
__device__ float g_mask_feats[16 * MAXN];  // transposed [16][N]
__device__ float g_kern_feats[16 * MAXN];  // transposed [16][N]
__device__ float g_s[4 * MAXN];            // nms fallback only
__device__ int   g_bstart[8];
__device__ int   g_topk[I_CNT];
__device__ float g_ctr[I_CNT * 3];
__device__ float g_ck[I_CNT * 16];
__device__ int   g_cb[I_CNT];
__device__ float g_weights[I_CNT * 337];
__device__ float g_beff[I_CNT * 16];
__device__ float g_feat[I_CNT * 35];
__device__ float g_pairA[I_CNT * I_CNT * 35];
__device__ float g_pairB[I_CNT * I_CNT * 35];
__device__ double g_sum[64];
__device__ double g_sumsq[64];
__device__ float g_mean[64];
__device__ float g_rstd[64];
__device__ double g_sumM[64];      // merge-branch stats (separate from tower stats)
__device__ double g_sumsqM[64];
__device__ float g_meanM[64];
__device__ float g_rstdM[64];
__device__ unsigned int g_cnt;

// ---------------- f32x2 helpers (exact fp32, 2x fma throughput) ----------------
__device__ __forceinline__ ull pk2(float lo, float hi) {
    ull r; asm("mov.b64 %0, {%1, %2};" : "=l"(r) : "f"(lo), "f"(hi)); return r;
}
__device__ __forceinline__ void upk2(ull v, float& lo, float& hi) {
    asm("mov.b64 {%0, %1}, %2;" : "=f"(lo), "=f"(hi) : "l"(v));
}
__device__ __forceinline__ ull ffma2(ull a, ull b, ull c) {
    ull d; asm("fma.rn.f32x2 %0, %1, %2, %3;" : "=l"(d) : "l"(a), "l"(b), "l"(c)); return d;
}
__device__ __forceinline__ float fast_sigmoid(float x) {
    return __fdividef(1.f, 1.f + __expf(-x));
}

// ---------------- stats helpers ----------------
__global__ void zero_stats_kernel() {
    int t = threadIdx.x;
    if (t < 64) { g_sum[t] = 0.0; g_sumsq[t] = 0.0; g_sumM[t] = 0.0; g_sumsqM[t] = 0.0; }
    if (t == 0) g_cnt = 0;
}

__global__ void finalize_statsM_kernel(int count, int dim) {
    int d = threadIdx.x;
    if (d < dim) {
        double m = g_sumM[d] / (double)count;
        double v = g_sumsqM[d] / (double)count - m * m;
        g_meanM[d] = (float)m;
        g_rstdM[d] = (float)(1.0 / sqrt(v + 1e-5));
    }
    if (d < 64) { g_sumM[d] = 0.0; g_sumsqM[d] = 0.0; }
}

// ---------------- fused tower layer 0: row-major input, smem transpose ----------------
__global__ __launch_bounds__(256) void layer0_kernel(
    const float* __restrict__ in,
    const float* __restrict__ Wm, const float* __restrict__ Wk,
    float* __restrict__ out, int N)
{
    __shared__ float xs[256][33];
    __shared__ ull wp[1024];

    int tid = threadIdx.x;
    for (int t = tid; t < 1024; t += 256) wp[t] = pk2(Wm[t], Wk[t]);

    int n0 = blockIdx.x * 256;
    int npts = N - n0; if (npts > 256) npts = 256;
    for (int idx = tid; idx < npts * 32; idx += 256)
        xs[idx >> 5][idx & 31] = in[(size_t)n0 * 32 + idx];
    __syncthreads();

    if (tid >= npts) return;
    int n = n0 + tid;

    ull acc[32];
#pragma unroll
    for (int d = 0; d < 32; d++) acc[d] = 0ull;

#pragma unroll
    for (int c = 0; c < 32; c++) {
        float z = xs[tid][c];
        ull zz = pk2(z, z);
        const ull* w = &wp[c * 32];
#pragma unroll
        for (int d = 0; d < 32; d++) acc[d] = ffma2(zz, w[d], acc[d]);
    }
#pragma unroll
    for (int d = 0; d < 32; d++) {
        float lo, hi; upk2(acc[d], lo, hi);
        out[(size_t)d * N + n] = lo;
        out[(size_t)(32 + d) * N + n] = hi;
    }
}

// ---------------- fused tower BN layer ----------------
__global__ __launch_bounds__(256) void layerBN_kernel(
    const float* __restrict__ in,
    const float* __restrict__ Wm, const float* __restrict__ Wk,
    float* __restrict__ out, int N)
{
    __shared__ ull wp[1024];
    __shared__ float sm[64], sr[64];
    int tid = threadIdx.x;
    for (int t = tid; t < 1024; t += 256) wp[t] = pk2(Wm[t], Wk[t]);
    if (tid < 64) { sm[tid] = g_mean[tid]; sr[tid] = g_rstd[tid]; }
    __syncthreads();

    int n = blockIdx.x * 256 + tid;
    if (n >= N) return;

    ull acc[32];
#pragma unroll
    for (int d = 0; d < 32; d++) acc[d] = 0ull;

#pragma unroll
    for (int c = 0; c < 32; c++) {
        float xm = in[(size_t)c * N + n];
        float xk = in[(size_t)(32 + c) * N + n];
        xm = fmaxf((xm - sm[c]) * sr[c], 0.f);
        xk = fmaxf((xk - sm[32 + c]) * sr[32 + c], 0.f);
        ull zz = pk2(xm, xk);
        const ull* w = &wp[c * 32];
#pragma unroll
        for (int d = 0; d < 32; d++) acc[d] = ffma2(zz, w[d], acc[d]);
    }
#pragma unroll
    for (int d = 0; d < 32; d++) {
        float lo, hi; upk2(acc[d], lo, hi);
        out[(size_t)d * N + n] = lo;
        out[(size_t)(32 + d) * N + n] = hi;
    }
}

// ---------------- fused tower output layer ----------------
__global__ __launch_bounds__(256) void layerOut_kernel(
    const float* __restrict__ in,
    const float* __restrict__ WmO, const float* __restrict__ WkO,
    const float* __restrict__ bm, const float* __restrict__ bk,
    float* __restrict__ om, float* __restrict__ ok, int N)
{
    __shared__ ull wp[512];
    __shared__ float sm[64], sr[64];
    __shared__ ull bb[16];
    int tid = threadIdx.x;
    for (int t = tid; t < 512; t += 256) wp[t] = pk2(WmO[t], WkO[t]);
    if (tid < 64) { sm[tid] = g_mean[tid]; sr[tid] = g_rstd[tid]; }
    if (tid < 16) bb[tid] = pk2(bm[tid], bk[tid]);
    __syncthreads();

    int n = blockIdx.x * 256 + tid;
    if (n >= N) return;

    ull acc[16];
#pragma unroll
    for (int d = 0; d < 16; d++) acc[d] = bb[d];

#pragma unroll
    for (int c = 0; c < 32; c++) {
        float xm = in[(size_t)c * N + n];
        float xk = in[(size_t)(32 + c) * N + n];
        xm = fmaxf((xm - sm[c]) * sr[c], 0.f);
        xk = fmaxf((xk - sm[32 + c]) * sr[32 + c], 0.f);
        ull zz = pk2(xm, xk);
        const ull* w = &wp[c * 16];
#pragma unroll
        for (int d = 0; d < 16; d++) acc[d] = ffma2(zz, w[d], acc[d]);
    }
#pragma unroll
    for (int d = 0; d < 16; d++) {
        float lo, hi; upk2(acc[d], lo, hi);
        om[(size_t)d * N + n] = lo;
        ok[(size_t)d * N + n] = hi;
    }
}

// ---------------- tower stats [64][N]; last block finalizes ----------------
__global__ __launch_bounds__(256) void stats64_kernel(const float* __restrict__ in, int N)
{
    int c = blockIdx.y;
    int tid = threadIdx.x;
    float s = 0.f, q = 0.f;
    for (int n = blockIdx.x * 256 + tid; n < N; n += 256 * gridDim.x) {
        float v = in[(size_t)c * N + n];
        s += v; q = fmaf(v, v, q);
    }
#pragma unroll
    for (int o = 16; o > 0; o >>= 1) {
        s += __shfl_down_sync(0xffffffffu, s, o);
        q += __shfl_down_sync(0xffffffffu, q, o);
    }
    __shared__ float ws[8], wq[8];
    if ((tid & 31) == 0) { ws[tid >> 5] = s; wq[tid >> 5] = q; }
    __syncthreads();
    if (tid == 0) {
        for (int w = 1; w < 8; w++) { s += ws[w]; q += wq[w]; }
        atomicAdd(&g_sum[c], (double)s);
        atomicAdd(&g_sumsq[c], (double)q);
        __threadfence();
        unsigned int t = atomicAdd(&g_cnt, 1u);
        if (t == gridDim.x * gridDim.y - 1) {
            for (int ch = 0; ch < 64; ch++) {
                double m = g_sum[ch] / (double)N;
                double v = g_sumsq[ch] / (double)N - m * m;
                g_mean[ch] = (float)m;
                g_rstd[ch] = (float)(1.0 / sqrt(v + 1e-5));
                g_sum[ch] = 0.0; g_sumsq[ch] = 0.0;
            }
            g_cnt = 0;
        }
    }
}

// ---------------- merge-branch layer (uses M-stats, safe to overlap with masks) ----------------
template <int DIN, int DOUT, bool BN, bool STATS, bool BIAS>
__global__ __launch_bounds__(256) void layerM_kernel(
    const float* __restrict__ in, const float* __restrict__ W,
    const float* __restrict__ bias, float* __restrict__ out, int N)
{
    __shared__ float Ws[DIN * DOUT];
    __shared__ float sb[DOUT];
    __shared__ float sm[DIN], sr[DIN];
    __shared__ double bs[DOUT], bq[DOUT];

    for (int t = threadIdx.x; t < DIN * DOUT; t += blockDim.x) Ws[t] = W[t];
    if (threadIdx.x < DOUT) sb[threadIdx.x] = BIAS ? bias[threadIdx.x] : 0.f;
    if (BN && threadIdx.x < DIN) {
        sm[threadIdx.x] = g_meanM[threadIdx.x];
        sr[threadIdx.x] = g_rstdM[threadIdx.x];
    }
    if (STATS && threadIdx.x < DOUT) { bs[threadIdx.x] = 0.0; bq[threadIdx.x] = 0.0; }
    __syncthreads();

    int n = blockIdx.x * blockDim.x + threadIdx.x;
    bool valid = (n < N);
    float acc[DOUT];
#pragma unroll
    for (int d = 0; d < DOUT; d++) acc[d] = sb[d];

    if (valid) {
#pragma unroll
        for (int c = 0; c < DIN; c++) {
            float xv = in[(size_t)n * DIN + c];
            if (BN) xv = fmaxf((xv - sm[c]) * sr[c], 0.f);
#pragma unroll
            for (int d = 0; d < DOUT; d++) acc[d] = fmaf(xv, Ws[c * DOUT + d], acc[d]);
        }
#pragma unroll
        for (int d = 0; d < DOUT; d++) out[(size_t)n * DOUT + d] = acc[d];
    }

    if (STATS) {
#pragma unroll
        for (int d = 0; d < DOUT; d++) {
            float v = valid ? acc[d] : 0.f;
            float v2 = v * v;
#pragma unroll
            for (int o = 16; o > 0; o >>= 1) {
                v  += __shfl_down_sync(0xffffffffu, v, o);
                v2 += __shfl_down_sync(0xffffffffu, v2, o);
            }
            if ((threadIdx.x & 31) == 0) {
                atomicAdd(&bs[d], (double)v);
                atomicAdd(&bq[d], (double)v2);
            }
        }
        __syncthreads();
        if (threadIdx.x < DOUT) {
            atomicAdd(&g_sumM[threadIdx.x], bs[threadIdx.x]);
            atomicAdd(&g_sumsqM[threadIdx.x], bq[threadIdx.x]);
        }
    }
}

// ---------------- batch ranges ----------------
__global__ void batch_ranges_kernel(const int* __restrict__ bidx, int N) {
    int n = blockIdx.x * blockDim.x + threadIdx.x;
    if (n >= N) return;
    int b = bidx[n];
    int pb = (n == 0) ? -1 : bidx[n - 1];
    for (int x = pb + 1; x <= b; x++) g_bstart[x] = n;
    if (n == N - 1) for (int x = b + 1; x <= 4; x++) g_bstart[x] = N;
}

// ---------------- fused top-K NMS ----------------
__global__ __launch_bounds__(1024) void nms_kernel(
    const float* __restrict__ heat, const float* __restrict__ coords, int N)
{
    extern __shared__ float ss[];
    __shared__ float wv[32];
    __shared__ int   wix[32];
    __shared__ float scx, scy, scz;

    int b = blockIdx.x, tid = threadIdx.x;
    int s0 = g_bstart[b], s1 = g_bstart[b + 1];
    int cnt = s1 - s0;
    float* s = (cnt <= NMS_CAP) ? (ss - s0) : (g_s + (size_t)b * N);

    float bv = -INFINITY; int bi = 0;
    for (int n = s0 + tid; n < s1; n += 1024) {
        float v = heat[n];
        s[n] = v;
        if (v > bv) { bv = v; bi = n; }
    }

    for (int k = 0; ; k++) {
#pragma unroll
        for (int o = 16; o > 0; o >>= 1) {
            float ov = __shfl_down_sync(0xffffffffu, bv, o);
            int   oi = __shfl_down_sync(0xffffffffu, bi, o);
            if (ov > bv || (ov == bv && oi < bi)) { bv = ov; bi = oi; }
        }
        if ((tid & 31) == 0) { wv[tid >> 5] = bv; wix[tid >> 5] = bi; }
        __syncthreads();
        if (tid < 32) {
            bv = wv[tid]; bi = wix[tid];
#pragma unroll
            for (int o = 16; o > 0; o >>= 1) {
                float ov = __shfl_down_sync(0xffffffffu, bv, o);
                int   oi = __shfl_down_sync(0xffffffffu, bi, o);
                if (ov > bv || (ov == bv && oi < bi)) { bv = ov; bi = oi; }
            }
            if (tid == 0) {
                g_topk[b * 32 + k] = bi;
                scx = coords[bi * 3]; scy = coords[bi * 3 + 1]; scz = coords[bi * 3 + 2];
            }
        }
        __syncthreads();
        if (k == 31) break;

        float cx = scx, cy = scy, cz = scz;
        bv = -INFINITY; bi = 0;
#pragma unroll 4
        for (int n = s0 + tid; n < s1; n += 1024) {
            float v = s[n];
            if (v != -INFINITY) {
                float dx = __fadd_rn(coords[n * 3],     -cx);
                float dy = __fadd_rn(coords[n * 3 + 1], -cy);
                float dz = __fadd_rn(coords[n * 3 + 2], -cz);
                float d2 = __fadd_rn(__fadd_rn(__fmul_rn(dx, dx), __fmul_rn(dy, dy)),
                                     __fmul_rn(dz, dz));
                if (d2 < 0.09f) { v = -INFINITY; s[n] = v; }
            }
            if (v > bv || (v == bv && n < bi)) { bv = v; bi = n; }
        }
    }
}

// ---------------- gather selected candidates ----------------
__global__ void gather_kernel(const float* __restrict__ coords, const int* __restrict__ bidx, int N) {
    int i = threadIdx.x;
    int idx = g_topk[i];
    float c0 = coords[idx * 3], c1 = coords[idx * 3 + 1], c2 = coords[idx * 3 + 2];
    g_ctr[i * 3] = c0; g_ctr[i * 3 + 1] = c1; g_ctr[i * 3 + 2] = c2;
    g_cb[i] = bidx[idx];
    for (int c = 0; c < 16; c++) {
        float kf = g_kern_feats[(size_t)c * N + idx];
        float mf = g_mask_feats[(size_t)c * N + idx];
        g_ck[i * 16 + c] = kf;
        g_feat[i * 35 + c] = kf;
        g_feat[i * 35 + 16 + c] = mf;
    }
    g_feat[i * 35 + 32] = c0;
    g_feat[i * 35 + 33] = c1;
    g_feat[i * 35 + 34] = c2;
}

// ---------------- weight generator ----------------
__global__ void weights_kernel(const float* __restrict__ Wwg, const float* __restrict__ bwg) {
    int i = blockIdx.x, j = threadIdx.x;
    if (j >= 337) return;
    float a = bwg[j];
#pragma unroll
    for (int c = 0; c < 16; c++) a = fmaf(g_ck[i * 16 + c], Wwg[c * 337 + j], a);
    g_weights[i * 337 + j] = a;
}

__global__ void beff_kernel() {
    int i = blockIdx.x, h = threadIdx.x;
    const float* wi = g_weights + i * 337;
    float b = wi[304 + h];
#pragma unroll
    for (int p = 0; p < 3; p++) b -= g_ctr[i * 3 + p] * wi[(16 + p) * 16 + h];
    g_beff[i * 16 + h] = b;
}

// ---------------- dynamic-conv masks: 256-point tiles, dynamic smem ----------------
__global__ __launch_bounds__(256) void masks_kernel(
    const float* __restrict__ coords, float* __restrict__ out, int N, int outw)
{
    extern __shared__ float dyn[];
    float* zs = dyn;                    // [19][MTILE+2] stride 258 (8B-aligned rows)
    float* ot = dyn + 19 * (MTILE + 2); // [32][MTILE+1] stride 257

    int i_base = blockIdx.y * 32;
    int n0 = blockIdx.x * MTILE;
    int tid = threadIdx.x;
    int i_local = tid >> 3;
    int hg = tid & 7;
    int i = i_base + i_local;
    int h0 = hg * 2;

    const float* wi = g_weights + i * 337;
    ull w0[19], w1[19];
#pragma unroll
    for (int r = 0; r < 19; r++) {
        float a = wi[r * 16 + h0], b = wi[r * 16 + h0 + 1];
        w0[r] = pk2(a, a);
        w1[r] = pk2(b, b);
    }
    float be0f = g_beff[i * 16 + h0], be1f = g_beff[i * 16 + h0 + 1];
    ull be0 = pk2(be0f, be0f), be1 = pk2(be1f, be1f);
    float w2a = wi[320 + h0], w2b = wi[320 + h0 + 1];
    float b2 = wi[336];

    // coalesced staging from transposed mask_feats
    for (int idx = tid; idx < 16 * MTILE; idx += 256) {
        int c = idx >> 8, p = idx & (MTILE - 1);
        int n = n0 + p;
        zs[c * (MTILE + 2) + p] = (n < N) ? g_mask_feats[(size_t)c * N + n] : 0.f;
    }
    for (int idx = tid; idx < MTILE * 3; idx += 256) {
        int p = idx / 3, c = idx % 3;
        int n = n0 + p;
        zs[(16 + c) * (MTILE + 2) + p] = (n < N) ? coords[(size_t)n * 3 + c] : 0.f;
    }
    __syncthreads();

#pragma unroll 2
    for (int pp = 0; pp < MTILE / 2; pp++) {
        ull a0 = be0, a1 = be1;
#pragma unroll
        for (int r = 0; r < 19; r++) {
            ull z = *(const ull*)&zs[r * (MTILE + 2) + pp * 2];
            a0 = ffma2(z, w0[r], a0);
            a1 = ffma2(z, w1[r], a1);
        }
        float a0l, a0h, a1l, a1h;
        upk2(a0, a0l, a0h);
        upk2(a1, a1l, a1h);
        float pl = fmaf(fmaxf(a0l, 0.f), w2a, fmaxf(a1l, 0.f) * w2b);
        float ph = fmaf(fmaxf(a0h, 0.f), w2a, fmaxf(a1h, 0.f) * w2b);
        pl += __shfl_down_sync(0xffffffffu, pl, 4, 8);
        ph += __shfl_down_sync(0xffffffffu, ph, 4, 8);
        pl += __shfl_down_sync(0xffffffffu, pl, 2, 8);
        ph += __shfl_down_sync(0xffffffffu, ph, 2, 8);
        pl += __shfl_down_sync(0xffffffffu, pl, 1, 8);
        ph += __shfl_down_sync(0xffffffffu, ph, 1, 8);
        if (hg == 0) {
            ot[i_local * (MTILE + 1) + pp * 2]     = fast_sigmoid(pl + b2);
            ot[i_local * (MTILE + 1) + pp * 2 + 1] = fast_sigmoid(ph + b2);
        }
    }
    __syncthreads();

    for (int idx = tid; idx < 32 * MTILE; idx += 256) {
        int il = idx >> 8, p = idx & (MTILE - 1);
        int n = n0 + p;
        if (n < N) out[(size_t)(i_base + il) * outw + n] = ot[il * (MTILE + 1) + p];
    }
}

// ---------------- merge branch ----------------
__global__ void diff_kernel() {
    int p = blockIdx.x * blockDim.x + threadIdx.x;
    if (p >= I_CNT * I_CNT) return;
    int i = p >> 7, j = p & 127;
#pragma unroll
    for (int c = 0; c < 35; c++)
        g_pairA[(size_t)p * 35 + c] = fmaxf(fabsf(g_feat[i * 35 + c] - g_feat[j * 35 + c]), 1e-6f);
}

__global__ void merge_out_kernel(const float* __restrict__ WgOut, const float* __restrict__ bg,
                                 float* __restrict__ out, int N, int outw) {
    int p = blockIdx.x * blockDim.x + threadIdx.x;
    if (p >= I_CNT * I_CNT) return;
    int i = p >> 7, j = p & 127;
    float a = bg[0];
#pragma unroll
    for (int c = 0; c < 35; c++) {
        float xv = g_pairB[(size_t)p * 35 + c];
        xv = fmaxf((xv - g_meanM[c]) * g_rstdM[c], 0.f);
        a = fmaf(xv, WgOut[c], a);
    }
    float m = (g_cb[i] != g_cb[j]) ? 0.f : fast_sigmoid(a);
    out[(size_t)i * outw + N + j] = m;
}

// ---------------- launcher (two-stream fork/join inside graph capture) ----------------
extern "C" void kernel_launch(void* const* d_in, const int* in_sizes, int n_in,
                              void* d_out, int out_size)
{
    const float* output_feats = (const float*)d_in[0];
    const float* coords       = (const float*)d_in[1];
    const float* heat         = (const float*)d_in[2];
    const int*   batch_idxs   = (const int*)d_in[3];
    const float* Wm     = (const float*)d_in[4];
    const float* Wm_out = (const float*)d_in[5];
    const float* bm_out = (const float*)d_in[6];
    const float* Wk     = (const float*)d_in[7];
    const float* Wk_out = (const float*)d_in[8];
    const float* bk_out = (const float*)d_in[9];
    const float* Wg     = (const float*)d_in[10];
    const float* Wg_out = (const float*)d_in[11];
    const float* bg_out = (const float*)d_in[12];
    const float* Wwg    = (const float*)d_in[13];
    const float* bwg    = (const float*)d_in[14];
    float* out = (float*)d_out;

    int N = in_sizes[2];
    int outw = N + I_CNT;
    int nb = (N + 255) / 256;

    float *tA, *tB, *maskf, *kernf, *pairA, *pairB;
    cudaGetSymbolAddress((void**)&tA,    g_tA);
    cudaGetSymbolAddress((void**)&tB,    g_tB);
    cudaGetSymbolAddress((void**)&maskf, g_mask_feats);
    cudaGetSymbolAddress((void**)&kernf, g_kern_feats);
    cudaGetSymbolAddress((void**)&pairA, g_pairA);
    cudaGetSymbolAddress((void**)&pairB, g_pairB);

    const int MASK_SMEM = (19 * (MTILE + 2) + 32 * (MTILE + 1)) * (int)sizeof(float);

    static cudaStream_t s1;
    static cudaEvent_t evFork1, evJoin1, evFork2, evJoin2;
    static bool init_done = false;
    if (!init_done) {
        cudaFuncSetAttribute(nms_kernel, cudaFuncAttributeMaxDynamicSharedMemorySize,
                             NMS_CAP * (int)sizeof(float));
        cudaFuncSetAttribute(masks_kernel, cudaFuncAttributeMaxDynamicSharedMemorySize,
                             MASK_SMEM);
        cudaStreamCreateWithFlags(&s1, cudaStreamNonBlocking);
        cudaEventCreateWithFlags(&evFork1, cudaEventDisableTiming);
        cudaEventCreateWithFlags(&evJoin1, cudaEventDisableTiming);
        cudaEventCreateWithFlags(&evFork2, cudaEventDisableTiming);
        cudaEventCreateWithFlags(&evJoin2, cudaEventDisableTiming);
        init_done = true;
    }

    dim3 sg(8, 64);

    // common prologue on main stream
    zero_stats_kernel<<<1, 64>>>();
    batch_ranges_kernel<<<nb, 256>>>(batch_idxs, N);

    // fork 1: NMS on side stream, towers on main stream
    cudaEventRecord(evFork1, 0);
    cudaStreamWaitEvent(s1, evFork1, 0);
    nms_kernel<<<4, 1024, NMS_CAP * sizeof(float), s1>>>(heat, coords, N);
    cudaEventRecord(evJoin1, s1);

    layer0_kernel<<<nb, 256>>>(output_feats, Wm, Wk, tA, N);
    stats64_kernel<<<sg, 256>>>(tA, N);
    layerBN_kernel<<<nb, 256>>>(tA, Wm + 1024, Wk + 1024, tB, N);
    stats64_kernel<<<sg, 256>>>(tB, N);
    layerBN_kernel<<<nb, 256>>>(tB, Wm + 2048, Wk + 2048, tA, N);
    stats64_kernel<<<sg, 256>>>(tA, N);
    layerOut_kernel<<<nb, 256>>>(tA, Wm_out, Wk_out, bm_out, bk_out, maskf, kernf, N);

    // join 1: gather needs both towers and NMS
    cudaStreamWaitEvent(0, evJoin1, 0);
    gather_kernel<<<1, 128>>>(coords, batch_idxs, N);
    weights_kernel<<<128, 352>>>(Wwg, bwg);

    // fork 2: merge branch on side stream, masks on main stream
    cudaEventRecord(evFork2, 0);
    cudaStreamWaitEvent(s1, evFork2, 0);
    diff_kernel<<<64, 256, 0, s1>>>();
    layerM_kernel<35, 35, false, true, false><<<64, 256, 0, s1>>>(pairA, Wg,        nullptr, pairB, I_CNT * I_CNT);
    finalize_statsM_kernel<<<1, 64, 0, s1>>>(I_CNT * I_CNT, 35);
    layerM_kernel<35, 35, true,  true, false><<<64, 256, 0, s1>>>(pairB, Wg + 1225, nullptr, pairA, I_CNT * I_CNT);
    finalize_statsM_kernel<<<1, 64, 0, s1>>>(I_CNT * I_CNT, 35);
    layerM_kernel<35, 35, true,  true, false><<<64, 256, 0, s1>>>(pairA, Wg + 2450, nullptr, pairB, I_CNT * I_CNT);
    finalize_statsM_kernel<<<1, 64, 0, s1>>>(I_CNT * I_CNT, 35);
    merge_out_kernel<<<64, 256, 0, s1>>>(Wg_out, bg_out, out, N, outw);
    cudaEventRecord(evJoin2, s1);

    beff_kernel<<<128, 16>>>();
    dim3 mg((N + MTILE - 1) / MTILE, 4);
    masks_kernel<<<mg, 256, MASK_SMEM>>>(coords, out, N, outw);

    // join 2
    cudaStreamWaitEvent(0, evJoin2, 0);
}

// round 7
// speedup vs baseline: 1.7304x; 1.2148x over previous
#include <cuda_runtime.h>
#include <math.h>

#define MAXN 100000
#define I_CNT 128
#define NMS_CAP 50000
#define MTILE 256

typedef unsigned long long ull;

// ---------------- device scratch (no allocations allowed) ----------------
__device__ float g_tA[64 * MAXN];          // transposed activations [64][N]
__device__ float g_tB[64 * MAXN];
__device__ float g_mask_feats[16 * MAXN];  // transposed [16][N]
__device__ float g_kern_feats[16 * MAXN];  // transposed [16][N]
__device__ float g_s[4 * MAXN];            // nms fallback only
__device__ int   g_bstart[8];
__device__ int   g_topk[I_CNT];
__device__ float g_ctr[I_CNT * 3];
__device__ float g_ck[I_CNT * 16];
__device__ int   g_cb[I_CNT];
__device__ float g_weights[I_CNT * 337];
__device__ float g_beff[I_CNT * 16];
__device__ float g_feat[I_CNT * 35];
__device__ float g_pairA[I_CNT * I_CNT * 35];
__device__ float g_pairB[I_CNT * I_CNT * 35];
__device__ float g_sumF[64];               // tower stats (float, fused path)
__device__ float g_sumsqF[64];
__device__ float g_mean[64];
__device__ float g_rstd[64];
__device__ double g_sumM[64];              // merge-branch stats
__device__ double g_sumsqM[64];
__device__ float g_meanM[64];
__device__ float g_rstdM[64];

// ---------------- f32x2 helpers ----------------
__device__ __forceinline__ ull pk2(float lo, float hi) {
    ull r; asm("mov.b64 %0, {%1, %2};" : "=l"(r) : "f"(lo), "f"(hi)); return r;
}
__device__ __forceinline__ void upk2(ull v, float& lo, float& hi) {
    asm("mov.b64 {%0, %1}, %2;" : "=f"(lo), "=f"(hi) : "l"(v));
}
__device__ __forceinline__ ull ffma2(ull a, ull b, ull c) {
    ull d; asm("fma.rn.f32x2 %0, %1, %2, %3;" : "=l"(d) : "l"(a), "l"(b), "l"(c)); return d;
}
__device__ __forceinline__ float fast_sigmoid(float x) {
    return __fdividef(1.f, 1.f + __expf(-x));
}

// ---------------- stats helpers ----------------
__global__ void zero_stats_kernel() {
    int t = threadIdx.x;
    if (t < 64) { g_sumF[t] = 0.f; g_sumsqF[t] = 0.f; g_sumM[t] = 0.0; g_sumsqM[t] = 0.0; }
}

// finalize tower stats from float accumulators; zero for next layer
__global__ void finalizeF_kernel(int count) {
    int d = threadIdx.x;
    if (d < 64) {
        double m = (double)g_sumF[d] / (double)count;
        double v = (double)g_sumsqF[d] / (double)count - m * m;
        g_mean[d] = (float)m;
        g_rstd[d] = (float)(1.0 / sqrt(v + 1e-5));
        g_sumF[d] = 0.f; g_sumsqF[d] = 0.f;
    }
}

__global__ void finalize_statsM_kernel(int count, int dim) {
    int d = threadIdx.x;
    if (d < dim) {
        double m = g_sumM[d] / (double)count;
        double v = g_sumsqM[d] / (double)count - m * m;
        g_meanM[d] = (float)m;
        g_rstdM[d] = (float)(1.0 / sqrt(v + 1e-5));
    }
    if (d < 64) { g_sumM[d] = 0.0; g_sumsqM[d] = 0.0; }
}

// ---------------- layer 0: row-major input, smem transpose, fused stats ----------------
__global__ __launch_bounds__(256) void layer0_kernel(
    const float* __restrict__ in,
    const float* __restrict__ Wm, const float* __restrict__ Wk,
    float* __restrict__ out, int N)
{
    __shared__ float xs[256][33];
    __shared__ ull wp[1024];
    __shared__ float bsum[64], bsq[64];

    int tid = threadIdx.x;
    for (int t = tid; t < 1024; t += 256) wp[t] = pk2(Wm[t], Wk[t]);
    if (tid < 64) { bsum[tid] = 0.f; bsq[tid] = 0.f; }

    int n0 = blockIdx.x * 256;
    int npts = N - n0; if (npts > 256) npts = 256;
    for (int idx = tid; idx < npts * 32; idx += 256)
        xs[idx >> 5][idx & 31] = in[(size_t)n0 * 32 + idx];
    __syncthreads();

    int n = n0 + tid;
    bool valid = (tid < npts);

    ull acc[32];
#pragma unroll
    for (int d = 0; d < 32; d++) acc[d] = 0ull;

    if (valid) {
#pragma unroll
        for (int c = 0; c < 32; c++) {
            float z = xs[tid][c];
            ull zz = pk2(z, z);
            const ull* w = &wp[c * 32];
#pragma unroll
            for (int d = 0; d < 32; d++) acc[d] = ffma2(zz, w[d], acc[d]);
        }
    }
#pragma unroll
    for (int d = 0; d < 32; d++) {
        float lo, hi; upk2(acc[d], lo, hi);
        if (valid) {
            out[(size_t)d * N + n] = lo;
            out[(size_t)(32 + d) * N + n] = hi;
        } else { lo = 0.f; hi = 0.f; }
        float ql = lo * lo, qh = hi * hi;
#pragma unroll
        for (int o = 16; o > 0; o >>= 1) {
            lo += __shfl_down_sync(0xffffffffu, lo, o);
            hi += __shfl_down_sync(0xffffffffu, hi, o);
            ql += __shfl_down_sync(0xffffffffu, ql, o);
            qh += __shfl_down_sync(0xffffffffu, qh, o);
        }
        if ((tid & 31) == 0) {
            atomicAdd(&bsum[d], lo);      atomicAdd(&bsq[d], ql);
            atomicAdd(&bsum[32 + d], hi); atomicAdd(&bsq[32 + d], qh);
        }
    }
    __syncthreads();
    if (tid < 64) {
        atomicAdd(&g_sumF[tid], bsum[tid]);
        atomicAdd(&g_sumsqF[tid], bsq[tid]);
    }
}

// ---------------- BN layer v2: one tower per blockIdx.y, smem-staged input ----------------
template <bool STATS>
__global__ __launch_bounds__(256) void layerBN2_kernel(
    const float* __restrict__ in,
    const float* __restrict__ W0, const float* __restrict__ W1,
    float* __restrict__ out, int N)
{
    __shared__ float xs[32][258];
    __shared__ float ws[1024];
    __shared__ float sm[32], sr[32];
    __shared__ float bs[32], bq[32];

    int tid = threadIdx.x;
    int t = blockIdx.y;
    int cb = t * 32;
    const float* W = t ? W1 : W0;
    for (int i = tid; i < 1024; i += 256) ws[i] = W[i];
    if (tid < 32) {
        sm[tid] = g_mean[cb + tid];
        sr[tid] = g_rstd[cb + tid];
        if (STATS) { bs[tid] = 0.f; bq[tid] = 0.f; }
    }

    int n0 = blockIdx.x * 256;
    if ((n0 + 256 <= N) && ((N & 3) == 0)) {
        // batched float4 staging
        for (int idx = tid; idx < 32 * 64; idx += 256) {
            int c = idx >> 6, p4 = (idx & 63) * 4;
            float4 v = *(const float4*)(in + (size_t)(cb + c) * N + n0 + p4);
            xs[c][p4] = v.x; xs[c][p4 + 1] = v.y; xs[c][p4 + 2] = v.z; xs[c][p4 + 3] = v.w;
        }
    } else {
        for (int idx = tid; idx < 32 * 256; idx += 256) {
            int c = idx >> 8, p = idx & 255;
            int n = n0 + p;
            xs[c][p] = (n < N) ? in[(size_t)(cb + c) * N + n] : 0.f;
        }
    }
    __syncthreads();

    int n = n0 + tid;
    bool valid = (n < N);

    float acc[32];
#pragma unroll
    for (int d = 0; d < 32; d++) acc[d] = 0.f;

#pragma unroll
    for (int c = 0; c < 32; c++) {
        float x = fmaxf((xs[c][tid] - sm[c]) * sr[c], 0.f);
        const float* w = &ws[c * 32];
#pragma unroll
        for (int d = 0; d < 32; d++) acc[d] = fmaf(x, w[d], acc[d]);
    }
    if (valid) {
#pragma unroll
        for (int d = 0; d < 32; d++) out[(size_t)(cb + d) * N + n] = acc[d];
    }

    if (STATS) {
#pragma unroll
        for (int d = 0; d < 32; d++) {
            float v = valid ? acc[d] : 0.f;
            float q = v * v;
#pragma unroll
            for (int o = 16; o > 0; o >>= 1) {
                v += __shfl_down_sync(0xffffffffu, v, o);
                q += __shfl_down_sync(0xffffffffu, q, o);
            }
            if ((tid & 31) == 0) { atomicAdd(&bs[d], v); atomicAdd(&bq[d], q); }
        }
        __syncthreads();
        if (tid < 32) {
            atomicAdd(&g_sumF[cb + tid], bs[tid]);
            atomicAdd(&g_sumsqF[cb + tid], bq[tid]);
        }
    }
}

// ---------------- output layer v2: one tower per blockIdx.y, smem-staged ----------------
__global__ __launch_bounds__(256) void layerOut2_kernel(
    const float* __restrict__ in,
    const float* __restrict__ W0, const float* __restrict__ W1,
    const float* __restrict__ b0, const float* __restrict__ b1,
    float* __restrict__ o0, float* __restrict__ o1, int N)
{
    __shared__ float xs[32][258];
    __shared__ float ws[512];
    __shared__ float sm[32], sr[32];
    __shared__ float bb[16];

    int tid = threadIdx.x;
    int t = blockIdx.y;
    int cb = t * 32;
    const float* W = t ? W1 : W0;
    const float* bias = t ? b1 : b0;
    float* out = t ? o1 : o0;
    for (int i = tid; i < 512; i += 256) ws[i] = W[i];
    if (tid < 32) { sm[tid] = g_mean[cb + tid]; sr[tid] = g_rstd[cb + tid]; }
    if (tid < 16) bb[tid] = bias[tid];

    int n0 = blockIdx.x * 256;
    if ((n0 + 256 <= N) && ((N & 3) == 0)) {
        for (int idx = tid; idx < 32 * 64; idx += 256) {
            int c = idx >> 6, p4 = (idx & 63) * 4;
            float4 v = *(const float4*)(in + (size_t)(cb + c) * N + n0 + p4);
            xs[c][p4] = v.x; xs[c][p4 + 1] = v.y; xs[c][p4 + 2] = v.z; xs[c][p4 + 3] = v.w;
        }
    } else {
        for (int idx = tid; idx < 32 * 256; idx += 256) {
            int c = idx >> 8, p = idx & 255;
            int n = n0 + p;
            xs[c][p] = (n < N) ? in[(size_t)(cb + c) * N + n] : 0.f;
        }
    }
    __syncthreads();

    int n = n0 + tid;
    if (n >= N) return;

    float acc[16];
#pragma unroll
    for (int d = 0; d < 16; d++) acc[d] = bb[d];

#pragma unroll
    for (int c = 0; c < 32; c++) {
        float x = fmaxf((xs[c][tid] - sm[c]) * sr[c], 0.f);
        const float* w = &ws[c * 16];
#pragma unroll
        for (int d = 0; d < 16; d++) acc[d] = fmaf(x, w[d], acc[d]);
    }
#pragma unroll
    for (int d = 0; d < 16; d++) out[(size_t)d * N + n] = acc[d];
}

// ---------------- merge-branch layer ----------------
template <int DIN, int DOUT, bool BN, bool STATS, bool BIAS>
__global__ __launch_bounds__(256) void layerM_kernel(
    const float* __restrict__ in, const float* __restrict__ W,
    const float* __restrict__ bias, float* __restrict__ out, int N)
{
    __shared__ float Ws[DIN * DOUT];
    __shared__ float sb[DOUT];
    __shared__ float sm[DIN], sr[DIN];
    __shared__ double bs[DOUT], bq[DOUT];

    for (int t = threadIdx.x; t < DIN * DOUT; t += blockDim.x) Ws[t] = W[t];
    if (threadIdx.x < DOUT) sb[threadIdx.x] = BIAS ? bias[threadIdx.x] : 0.f;
    if (BN && threadIdx.x < DIN) {
        sm[threadIdx.x] = g_meanM[threadIdx.x];
        sr[threadIdx.x] = g_rstdM[threadIdx.x];
    }
    if (STATS && threadIdx.x < DOUT) { bs[threadIdx.x] = 0.0; bq[threadIdx.x] = 0.0; }
    __syncthreads();

    int n = blockIdx.x * blockDim.x + threadIdx.x;
    bool valid = (n < N);
    float acc[DOUT];
#pragma unroll
    for (int d = 0; d < DOUT; d++) acc[d] = sb[d];

    if (valid) {
#pragma unroll
        for (int c = 0; c < DIN; c++) {
            float xv = in[(size_t)n * DIN + c];
            if (BN) xv = fmaxf((xv - sm[c]) * sr[c], 0.f);
#pragma unroll
            for (int d = 0; d < DOUT; d++) acc[d] = fmaf(xv, Ws[c * DOUT + d], acc[d]);
        }
#pragma unroll
        for (int d = 0; d < DOUT; d++) out[(size_t)n * DOUT + d] = acc[d];
    }

    if (STATS) {
#pragma unroll
        for (int d = 0; d < DOUT; d++) {
            float v = valid ? acc[d] : 0.f;
            float v2 = v * v;
#pragma unroll
            for (int o = 16; o > 0; o >>= 1) {
                v  += __shfl_down_sync(0xffffffffu, v, o);
                v2 += __shfl_down_sync(0xffffffffu, v2, o);
            }
            if ((threadIdx.x & 31) == 0) {
                atomicAdd(&bs[d], (double)v);
                atomicAdd(&bq[d], (double)v2);
            }
        }
        __syncthreads();
        if (threadIdx.x < DOUT) {
            atomicAdd(&g_sumM[threadIdx.x], bs[threadIdx.x]);
            atomicAdd(&g_sumsqM[threadIdx.x], bq[threadIdx.x]);
        }
    }
}

// ---------------- batch ranges ----------------
__global__ void batch_ranges_kernel(const int* __restrict__ bidx, int N) {
    int n = blockIdx.x * blockDim.x + threadIdx.x;
    if (n >= N) return;
    int b = bidx[n];
    int pb = (n == 0) ? -1 : bidx[n - 1];
    for (int x = pb + 1; x <= b; x++) g_bstart[x] = n;
    if (n == N - 1) for (int x = b + 1; x <= 4; x++) g_bstart[x] = N;
}

// ---------------- fused top-K NMS ----------------
__global__ __launch_bounds__(1024) void nms_kernel(
    const float* __restrict__ heat, const float* __restrict__ coords, int N)
{
    extern __shared__ float ss[];
    __shared__ float wv[32];
    __shared__ int   wix[32];
    __shared__ float scx, scy, scz;

    int b = blockIdx.x, tid = threadIdx.x;
    int s0 = g_bstart[b], s1 = g_bstart[b + 1];
    int cnt = s1 - s0;
    float* s = (cnt <= NMS_CAP) ? (ss - s0) : (g_s + (size_t)b * N);

    float bv = -INFINITY; int bi = 0;
    for (int n = s0 + tid; n < s1; n += 1024) {
        float v = heat[n];
        s[n] = v;
        if (v > bv) { bv = v; bi = n; }
    }

    for (int k = 0; ; k++) {
#pragma unroll
        for (int o = 16; o > 0; o >>= 1) {
            float ov = __shfl_down_sync(0xffffffffu, bv, o);
            int   oi = __shfl_down_sync(0xffffffffu, bi, o);
            if (ov > bv || (ov == bv && oi < bi)) { bv = ov; bi = oi; }
        }
        if ((tid & 31) == 0) { wv[tid >> 5] = bv; wix[tid >> 5] = bi; }
        __syncthreads();
        if (tid < 32) {
            bv = wv[tid]; bi = wix[tid];
#pragma unroll
            for (int o = 16; o > 0; o >>= 1) {
                float ov = __shfl_down_sync(0xffffffffu, bv, o);
                int   oi = __shfl_down_sync(0xffffffffu, bi, o);
                if (ov > bv || (ov == bv && oi < bi)) { bv = ov; bi = oi; }
            }
            if (tid == 0) {
                g_topk[b * 32 + k] = bi;
                scx = coords[bi * 3]; scy = coords[bi * 3 + 1]; scz = coords[bi * 3 + 2];
            }
        }
        __syncthreads();
        if (k == 31) break;

        float cx = scx, cy = scy, cz = scz;
        bv = -INFINITY; bi = 0;
#pragma unroll 4
        for (int n = s0 + tid; n < s1; n += 1024) {
            float v = s[n];
            if (v != -INFINITY) {
                float dx = __fadd_rn(coords[n * 3],     -cx);
                float dy = __fadd_rn(coords[n * 3 + 1], -cy);
                float dz = __fadd_rn(coords[n * 3 + 2], -cz);
                float d2 = __fadd_rn(__fadd_rn(__fmul_rn(dx, dx), __fmul_rn(dy, dy)),
                                     __fmul_rn(dz, dz));
                if (d2 < 0.09f) { v = -INFINITY; s[n] = v; }
            }
            if (v > bv || (v == bv && n < bi)) { bv = v; bi = n; }
        }
    }
}

// ---------------- gather selected candidates ----------------
__global__ void gather_kernel(const float* __restrict__ coords, const int* __restrict__ bidx, int N) {
    int i = threadIdx.x;
    int idx = g_topk[i];
    float c0 = coords[idx * 3], c1 = coords[idx * 3 + 1], c2 = coords[idx * 3 + 2];
    g_ctr[i * 3] = c0; g_ctr[i * 3 + 1] = c1; g_ctr[i * 3 + 2] = c2;
    g_cb[i] = bidx[idx];
    for (int c = 0; c < 16; c++) {
        float kf = g_kern_feats[(size_t)c * N + idx];
        float mf = g_mask_feats[(size_t)c * N + idx];
        g_ck[i * 16 + c] = kf;
        g_feat[i * 35 + c] = kf;
        g_feat[i * 35 + 16 + c] = mf;
    }
    g_feat[i * 35 + 32] = c0;
    g_feat[i * 35 + 33] = c1;
    g_feat[i * 35 + 34] = c2;
}

// ---------------- weight generator ----------------
__global__ void weights_kernel(const float* __restrict__ Wwg, const float* __restrict__ bwg) {
    int i = blockIdx.x, j = threadIdx.x;
    if (j >= 337) return;
    float a = bwg[j];
#pragma unroll
    for (int c = 0; c < 16; c++) a = fmaf(g_ck[i * 16 + c], Wwg[c * 337 + j], a);
    g_weights[i * 337 + j] = a;
}

__global__ void beff_kernel() {
    int i = blockIdx.x, h = threadIdx.x;
    const float* wi = g_weights + i * 337;
    float b = wi[304 + h];
#pragma unroll
    for (int p = 0; p < 3; p++) b -= g_ctr[i * 3 + p] * wi[(16 + p) * 16 + h];
    g_beff[i * 16 + h] = b;
}

// ---------------- dynamic-conv masks: 256-point tiles ----------------
__global__ __launch_bounds__(256) void masks_kernel(
    const float* __restrict__ coords, float* __restrict__ out, int N, int outw)
{
    extern __shared__ float dyn[];
    float* zs = dyn;                    // [19][MTILE+2]
    float* ot = dyn + 19 * (MTILE + 2); // [32][MTILE+1]

    int i_base = blockIdx.y * 32;
    int n0 = blockIdx.x * MTILE;
    int tid = threadIdx.x;
    int i_local = tid >> 3;
    int hg = tid & 7;
    int i = i_base + i_local;
    int h0 = hg * 2;

    const float* wi = g_weights + i * 337;
    ull w0[19], w1[19];
#pragma unroll
    for (int r = 0; r < 19; r++) {
        float a = wi[r * 16 + h0], b = wi[r * 16 + h0 + 1];
        w0[r] = pk2(a, a);
        w1[r] = pk2(b, b);
    }
    float be0f = g_beff[i * 16 + h0], be1f = g_beff[i * 16 + h0 + 1];
    ull be0 = pk2(be0f, be0f), be1 = pk2(be1f, be1f);
    float w2a = wi[320 + h0], w2b = wi[320 + h0 + 1];
    float b2 = wi[336];

    for (int idx = tid; idx < 16 * MTILE; idx += 256) {
        int c = idx >> 8, p = idx & (MTILE - 1);
        int n = n0 + p;
        zs[c * (MTILE + 2) + p] = (n < N) ? g_mask_feats[(size_t)c * N + n] : 0.f;
    }
    for (int idx = tid; idx < MTILE * 3; idx += 256) {
        int p = idx / 3, c = idx % 3;
        int n = n0 + p;
        zs[(16 + c) * (MTILE + 2) + p] = (n < N) ? coords[(size_t)n * 3 + c] : 0.f;
    }
    __syncthreads();

#pragma unroll 2
    for (int pp = 0; pp < MTILE / 2; pp++) {
        ull a0 = be0, a1 = be1;
#pragma unroll
        for (int r = 0; r < 19; r++) {
            ull z = *(const ull*)&zs[r * (MTILE + 2) + pp * 2];
            a0 = ffma2(z, w0[r], a0);
            a1 = ffma2(z, w1[r], a1);
        }
        float a0l, a0h, a1l, a1h;
        upk2(a0, a0l, a0h);
        upk2(a1, a1l, a1h);
        float pl = fmaf(fmaxf(a0l, 0.f), w2a, fmaxf(a1l, 0.f) * w2b);
        float ph = fmaf(fmaxf(a0h, 0.f), w2a, fmaxf(a1h, 0.f) * w2b);
        pl += __shfl_down_sync(0xffffffffu, pl, 4, 8);
        ph += __shfl_down_sync(0xffffffffu, ph, 4, 8);
        pl += __shfl_down_sync(0xffffffffu, pl, 2, 8);
        ph += __shfl_down_sync(0xffffffffu, ph, 2, 8);
        pl += __shfl_down_sync(0xffffffffu, pl, 1, 8);
        ph += __shfl_down_sync(0xffffffffu, ph, 1, 8);
        if (hg == 0) {
            ot[i_local * (MTILE + 1) + pp * 2]     = fast_sigmoid(pl + b2);
            ot[i_local * (MTILE + 1) + pp * 2 + 1] = fast_sigmoid(ph + b2);
        }
    }
    __syncthreads();

    for (int idx = tid; idx < 32 * MTILE; idx += 256) {
        int il = idx >> 8, p = idx & (MTILE - 1);
        int n = n0 + p;
        if (n < N) out[(size_t)(i_base + il) * outw + n] = ot[il * (MTILE + 1) + p];
    }
}

// ---------------- merge branch ----------------
__global__ void diff_kernel() {
    int p = blockIdx.x * blockDim.x + threadIdx.x;
    if (p >= I_CNT * I_CNT) return;
    int i = p >> 7, j = p & 127;
#pragma unroll
    for (int c = 0; c < 35; c++)
        g_pairA[(size_t)p * 35 + c] = fmaxf(fabsf(g_feat[i * 35 + c] - g_feat[j * 35 + c]), 1e-6f);
}

__global__ void merge_out_kernel(const float* __restrict__ WgOut, const float* __restrict__ bg,
                                 float* __restrict__ out, int N, int outw) {
    int p = blockIdx.x * blockDim.x + threadIdx.x;
    if (p >= I_CNT * I_CNT) return;
    int i = p >> 7, j = p & 127;
    float a = bg[0];
#pragma unroll
    for (int c = 0; c < 35; c++) {
        float xv = g_pairB[(size_t)p * 35 + c];
        xv = fmaxf((xv - g_meanM[c]) * g_rstdM[c], 0.f);
        a = fmaf(xv, WgOut[c], a);
    }
    float m = (g_cb[i] != g_cb[j]) ? 0.f : fast_sigmoid(a);
    out[(size_t)i * outw + N + j] = m;
}

// ---------------- launcher ----------------
extern "C" void kernel_launch(void* const* d_in, const int* in_sizes, int n_in,
                              void* d_out, int out_size)
{
    const float* output_feats = (const float*)d_in[0];
    const float* coords       = (const float*)d_in[1];
    const float* heat         = (const float*)d_in[2];
    const int*   batch_idxs   = (const int*)d_in[3];
    const float* Wm     = (const float*)d_in[4];
    const float* Wm_out = (const float*)d_in[5];
    const float* bm_out = (const float*)d_in[6];
    const float* Wk     = (const float*)d_in[7];
    const float* Wk_out = (const float*)d_in[8];
    const float* bk_out = (const float*)d_in[9];
    const float* Wg     = (const float*)d_in[10];
    const float* Wg_out = (const float*)d_in[11];
    const float* bg_out = (const float*)d_in[12];
    const float* Wwg    = (const float*)d_in[13];
    const float* bwg    = (const float*)d_in[14];
    float* out = (float*)d_out;

    int N = in_sizes[2];
    int outw = N + I_CNT;
    int nb = (N + 255) / 256;

    float *tA, *tB, *maskf, *kernf, *pairA, *pairB;
    cudaGetSymbolAddress((void**)&tA,    g_tA);
    cudaGetSymbolAddress((void**)&tB,    g_tB);
    cudaGetSymbolAddress((void**)&maskf, g_mask_feats);
    cudaGetSymbolAddress((void**)&kernf, g_kern_feats);
    cudaGetSymbolAddress((void**)&pairA, g_pairA);
    cudaGetSymbolAddress((void**)&pairB, g_pairB);

    const int MASK_SMEM = (19 * (MTILE + 2) + 32 * (MTILE + 1)) * (int)sizeof(float);

    static cudaStream_t s1;
    static cudaEvent_t evFork1, evJoin1, evFork2, evJoin2;
    static bool init_done = false;
    if (!init_done) {
        cudaFuncSetAttribute(nms_kernel, cudaFuncAttributeMaxDynamicSharedMemorySize,
                             NMS_CAP * (int)sizeof(float));
        cudaFuncSetAttribute(masks_kernel, cudaFuncAttributeMaxDynamicSharedMemorySize,
                             MASK_SMEM);
        cudaStreamCreateWithFlags(&s1, cudaStreamNonBlocking);
        cudaEventCreateWithFlags(&evFork1, cudaEventDisableTiming);
        cudaEventCreateWithFlags(&evJoin1, cudaEventDisableTiming);
        cudaEventCreateWithFlags(&evFork2, cudaEventDisableTiming);
        cudaEventCreateWithFlags(&evJoin2, cudaEventDisableTiming);
        init_done = true;
    }

    // prologue: ranges first so NMS can fork ASAP
    batch_ranges_kernel<<<nb, 256>>>(batch_idxs, N);

    cudaEventRecord(evFork1, 0);
    cudaStreamWaitEvent(s1, evFork1, 0);
    nms_kernel<<<4, 1024, NMS_CAP * sizeof(float), s1>>>(heat, coords, N);
    cudaEventRecord(evJoin1, s1);

    zero_stats_kernel<<<1, 64>>>();

    // tower chain: stats fused into producing layers
    dim3 g2(nb, 2);
    layer0_kernel<<<nb, 256>>>(output_feats, Wm, Wk, tA, N);
    finalizeF_kernel<<<1, 64>>>(N);
    layerBN2_kernel<true><<<g2, 256>>>(tA, Wm + 1024, Wk + 1024, tB, N);
    finalizeF_kernel<<<1, 64>>>(N);
    layerBN2_kernel<true><<<g2, 256>>>(tB, Wm + 2048, Wk + 2048, tA, N);
    finalizeF_kernel<<<1, 64>>>(N);
    layerOut2_kernel<<<g2, 256>>>(tA, Wm_out, Wk_out, bm_out, bk_out, maskf, kernf, N);

    // join 1
    cudaStreamWaitEvent(0, evJoin1, 0);
    gather_kernel<<<1, 128>>>(coords, batch_idxs, N);
    weights_kernel<<<128, 352>>>(Wwg, bwg);

    // fork 2: merge branch overlapped with masks
    cudaEventRecord(evFork2, 0);
    cudaStreamWaitEvent(s1, evFork2, 0);
    diff_kernel<<<64, 256, 0, s1>>>();
    layerM_kernel<35, 35, false, true, false><<<64, 256, 0, s1>>>(pairA, Wg,        nullptr, pairB, I_CNT * I_CNT);
    finalize_statsM_kernel<<<1, 64, 0, s1>>>(I_CNT * I_CNT, 35);
    layerM_kernel<35, 35, true,  true, false><<<64, 256, 0, s1>>>(pairB, Wg + 1225, nullptr, pairA, I_CNT * I_CNT);
    finalize_statsM_kernel<<<1, 64, 0, s1>>>(I_CNT * I_CNT, 35);
    layerM_kernel<35, 35, true,  true, false><<<64, 256, 0, s1>>>(pairA, Wg + 2450, nullptr, pairB, I_CNT * I_CNT);
    finalize_statsM_kernel<<<1, 64, 0, s1>>>(I_CNT * I_CNT, 35);
    merge_out_kernel<<<64, 256, 0, s1>>>(Wg_out, bg_out, out, N, outw);
    cudaEventRecord(evJoin2, s1);

    beff_kernel<<<128, 16>>>();
    dim3 mg((N + MTILE - 1) / MTILE, 4);
    masks_kernel<<<mg, 256, MASK_SMEM>>>(coords, out, N, outw);

    cudaStreamWaitEvent(0, evJoin2, 0);
}